// round 1
// baseline (speedup 1.0000x reference)
#include <cuda_runtime.h>
#include <cstdint>

// Problem constants (fixed by the reference's setup_inputs)
#define HH      200     // history length
#define NW      10      // warps per block
#define THREADS 320
#define PAIRS   100     // HH/2 position-pairs per batch row
#define PPW     (PAIRS / NW)

// ---------------------------------------------------------------------------
// Packed f32x2 helpers (sm_100+): one instruction = two fp32 FMAs, full
// precision. ptxas never auto-fuses these from C++; PTX only.
// ---------------------------------------------------------------------------
__device__ __forceinline__ unsigned long long ffma2(unsigned long long a,
                                                    unsigned long long b,
                                                    unsigned long long c) {
    unsigned long long d;
    asm("fma.rn.f32x2 %0, %1, %2, %3;" : "=l"(d) : "l"(a), "l"(b), "l"(c));
    return d;
}
__device__ __forceinline__ unsigned long long pack2(float lo, float hi) {
    unsigned long long d;
    asm("mov.b64 %0, {%1, %2};" : "=l"(d) : "f"(lo), "f"(hi));
    return d;
}
__device__ __forceinline__ float2 unpack2(unsigned long long v) {
    float lo, hi;
    asm("mov.b64 {%0, %1}, %2;" : "=f"(lo), "=f"(hi) : "l"(v));
    return make_float2(lo, hi);
}
__device__ __forceinline__ float sigm(float x) {
    return __fdividef(1.f, 1.f + __expf(-x));
}

// ---------------------------------------------------------------------------
// One block per batch row b. 10 warps; warp w handles position-pairs
// pp = w + 10*j (j = 0..9), i.e. history positions h = 2*pp, 2*pp+1.
//
// Within a warp:
//   * products phase : lane l owns embedding elements 2l, 2l+1
//                      (l<16 -> item-emb half, l>=16 -> region-emb half);
//                      each is one fully-coalesced LDG.64 off a 128B table row.
//   * MLP phase      : lane k owns hidden unit k; the 66 attn1 weights of
//                      column k live pre-packed as 32 x u64 (f32x2 pairs) in
//                      registers; products are read back as LDS.128 broadcasts
//                      and fed to FFMA2 with positions A/B in the two f32 lanes
//                      (wait - A/B pack is over the *pair index* i: acc lanes
//                      hold even/odd partial sums per position, 4 indep chains).
// ---------------------------------------------------------------------------
__global__ __launch_bounds__(THREADS, 1)
void nais_kernel(const int*   __restrict__ history,
                 const int*   __restrict__ target,
                 const int*   __restrict__ history_region,
                 const int*   __restrict__ target_region,
                 const float* __restrict__ lat_long,
                 const float* __restrict__ W_hist,
                 const float* __restrict__ W_tgt,
                 const float* __restrict__ W_reg,
                 const float* __restrict__ attn1_W,
                 const float* __restrict__ attn1_b,
                 const float* __restrict__ attn2_W,
                 const float* __restrict__ dist_W,
                 const float* __restrict__ dist_b,
                 float*       __restrict__ out)
{
    const int b    = blockIdx.x;
    const int tid  = threadIdx.x;
    const int w    = tid >> 5;
    const int lane = tid & 31;

    __shared__ __align__(16) float s_pA[NW][64];
    __shared__ __align__(16) float s_pB[NW][64];
    __shared__ float s_se[NW], s_sp[NW];

    // ---- per-lane MLP weights: column k of attn1_W, packed in (row,row+1) pairs
    unsigned long long wpair[32];
#pragma unroll
    for (int jj = 0; jj < 32; jj++) {
        wpair[jj] = pack2(attn1_W[(2 * jj) * 32 + lane],
                          attn1_W[(2 * jj + 1) * 32 + lane]);
    }
    const float wd0  = attn1_W[64 * 32 + lane];   // dist feature 0 row
    const float wd1  = attn1_W[65 * 32 + lane];   // dist feature 1 row
    const float bias = attn1_b[lane];
    const float w2k  = attn2_W[lane];

    // dist linear: out_j = sum_i (100*ll_i) * dist_W[i][j] + dist_b[j]
    const float dw00 = dist_W[0] * 100.f, dw01 = dist_W[1] * 100.f;
    const float dw10 = dist_W[2] * 100.f, dw11 = dist_W[3] * 100.f;
    const float db0  = dist_b[0],         db1  = dist_b[1];

    const int tgt  = target[b];
    const int treg = target_region[b];

    // target embedding values for this lane's element pair (2*lane, 2*lane+1)
    float t0, t1;
    if (lane < 16) {
        float2 t = *(const float2*)(W_tgt + (size_t)tgt * 32 + 2 * lane);
        t0 = t.x; t1 = t.y;
    } else {
        float2 t = *(const float2*)(W_reg + (size_t)treg * 32 + (2 * lane - 32));
        t0 = t.x; t1 = t.y;
    }

    const int base = b * HH;

    auto ld_idx = [&](int j, int& iA, int& iB, int& rA, int& rB) {
        int jj = (j < PPW) ? j : (PPW - 1);         // clamp (prefetch overrun)
        int h  = 2 * (w + NW * jj);
        iA = history[base + h];          iB = history[base + h + 1];
        rA = history_region[base + h];   rB = history_region[base + h + 1];
    };
    auto ld_emb = [&](int iA, int iB, int rA, int rB, float2& a, float2& c) {
        const float *pa, *pb;
        if (lane < 16) {
            pa = W_hist + (size_t)iA * 32 + 2 * lane;
            pb = W_hist + (size_t)iB * 32 + 2 * lane;
        } else {
            pa = W_reg + (size_t)rA * 32 + (2 * lane - 32);
            pb = W_reg + (size_t)rB * 32 + (2 * lane - 32);
        }
        a = *(const float2*)pa;
        c = *(const float2*)pb;
    };

    // ---- 2-deep software pipeline: indices 2 ahead, embeddings 1 ahead
    int iA0, iB0, rA0, rB0;     // current pair indices
    int iA1, iB1, rA1, rB1;     // next pair indices
    float2 eA, eB;              // current pair embeddings (this lane's 2 elems x2 pos)

    ld_idx(0, iA0, iB0, rA0, rB0);
    ld_idx(1, iA1, iB1, rA1, rB1);
    ld_emb(iA0, iB0, rA0, rB0, eA, eB);

    float sum_exp = 0.f, sum_pred = 0.f;

    for (int j = 0; j < PPW; j++) {
        // prefetch next pair's embeddings (idx already resident) + idx 2 ahead
        float2 neA, neB;
        ld_emb(iA1, iB1, rA1, rB1, neA, neB);
        int niA, niB, nrA, nrB;
        ld_idx(j + 2, niA, niB, nrA, nrB);

        const int h = 2 * (w + NW * j);
        float2 llA = *(const float2*)(lat_long + (size_t)(base + h) * 2);
        float2 llB = *(const float2*)(lat_long + (size_t)(base + h) * 2 + 2);

        // products p = h_emb * t_emb -> per-warp shared buffers
        float pA0 = eA.x * t0, pA1 = eA.y * t1;
        float pB0 = eB.x * t0, pB1 = eB.y * t1;
        *(float2*)&s_pA[w][2 * lane] = make_float2(pA0, pA1);
        *(float2*)&s_pB[w][2 * lane] = make_float2(pB0, pB1);
        __syncwarp();

        // hid_k = sum_i p_i * W1[i][k]  — 64 FFMA2, 32 broadcast LDS.128
        unsigned long long a0 = 0, a1 = 0, b0 = 0, b1 = 0;  // 4 indep chains
        const ulonglong2* qA = (const ulonglong2*)s_pA[w];
        const ulonglong2* qB = (const ulonglong2*)s_pB[w];
#pragma unroll
        for (int i = 0; i < 16; i++) {
            ulonglong2 xa = qA[i];   // (p[4i],p[4i+1]) | (p[4i+2],p[4i+3])
            ulonglong2 xb = qB[i];
            a0 = ffma2(xa.x, wpair[2 * i],     a0);
            a1 = ffma2(xa.y, wpair[2 * i + 1], a1);
            b0 = ffma2(xb.x, wpair[2 * i],     b0);
            b1 = ffma2(xb.y, wpair[2 * i + 1], b1);
        }
        float2 fa0 = unpack2(a0), fa1 = unpack2(a1);
        float2 fb0 = unpack2(b0), fb1 = unpack2(b1);

        // dist features (uniform across lanes; cheap)
        float dA0 = sigm(fmaf(llA.x, dw00, fmaf(llA.y, dw10, db0)));
        float dA1 = sigm(fmaf(llA.x, dw01, fmaf(llA.y, dw11, db1)));
        float dB0 = sigm(fmaf(llB.x, dw00, fmaf(llB.y, dw10, db0)));
        float dB1 = sigm(fmaf(llB.x, dw01, fmaf(llB.y, dw11, db1)));

        float hidA = fa0.x + fa0.y + fa1.x + fa1.y
                   + fmaf(dA0, wd0, fmaf(dA1, wd1, bias));
        float hidB = fb0.x + fb0.y + fb1.x + fb1.y
                   + fmaf(dB0, wd0, fmaf(dB1, wd1, bias));
        float vA = fmaxf(hidA, 0.f) * w2k;   // relu * attn2 column
        float vB = fmaxf(hidB, 0.f) * w2k;
        float sA = pA0 + pA1;                // partial dot(h_emb, t_emb)
        float sB = pB0 + pB1;

        // combined 4-value butterfly reduction
#pragma unroll
        for (int off = 16; off; off >>= 1) {
            vA += __shfl_xor_sync(0xffffffffu, vA, off);
            vB += __shfl_xor_sync(0xffffffffu, vB, off);
            sA += __shfl_xor_sync(0xffffffffu, sA, off);
            sB += __shfl_xor_sync(0xffffffffu, sB, off);
        }

        float eAx = (iA0 != tgt) ? __expf(vA) : 0.f;
        float eBx = (iB0 != tgt) ? __expf(vB) : 0.f;
        sum_exp  += eAx + eBx;
        sum_pred  = fmaf(eAx, sA, fmaf(eBx, sB, sum_pred));

        __syncwarp();   // all lanes done reading s_p before next iter's STS

        // rotate pipeline
        eA = neA; eB = neB;
        iA0 = iA1; iB0 = iB1; rA0 = rA1; rB0 = rB1;
        iA1 = niA; iB1 = niB; rA1 = nrA; rB1 = nrB;
    }

    if (lane == 0) { s_se[w] = sum_exp; s_sp[w] = sum_pred; }
    __syncthreads();
    if (tid == 0) {
        float se = 0.f, sp = 0.f;
#pragma unroll
        for (int i = 0; i < NW; i++) { se += s_se[i]; sp += s_sp[i]; }
        // attn_w = expA / sum^BETA, BETA=0.5 -> pred = sp / sqrt(se)
        float pred = sp / sqrtf(se);
        out[b] = __fdividef(1.f, 1.f + __expf(-pred));
    }
}

extern "C" void kernel_launch(void* const* d_in, const int* in_sizes, int n_in,
                              void* d_out, int out_size) {
    const int B = in_sizes[1];   // target is [B]
    nais_kernel<<<B, THREADS>>>(
        (const int*)  d_in[0],   // history [B,H]
        (const int*)  d_in[1],   // target [B]
        (const int*)  d_in[2],   // history_region [B,H]
        (const int*)  d_in[3],   // target_region [B]
        (const float*)d_in[4],   // target_lat_long [B,H,2]
        (const float*)d_in[5],   // W_hist
        (const float*)d_in[6],   // W_tgt
        (const float*)d_in[7],   // W_reg
        (const float*)d_in[8],   // attn1_W [66,32]
        (const float*)d_in[9],   // attn1_b [32]
        (const float*)d_in[10],  // attn2_W [32,1]
        (const float*)d_in[11],  // dist_W [2,2]
        (const float*)d_in[12],  // dist_b [2]
        (float*)d_out);
}

// round 2
// speedup vs baseline: 1.6440x; 1.6440x over previous
#include <cuda_runtime.h>
#include <cuda_fp16.h>
#include <cstdint>

// Problem constants (fixed by the reference's setup_inputs)
#define HH      200     // history length
#define NW      4       // warps per block
#define THREADS 128
#define PAIRS   100     // HH/2 position-pairs per batch row
#define PPW     (PAIRS / NW)   // 25
#define VSTRIDE 36      // words per position row in s_vs (16B-aligned, conflict-free)

// ---------------------------------------------------------------------------
// Packed f32x2 helpers (sm_100+): one instruction = two fp32 FMAs, full
// precision. ptxas never auto-fuses these from C++; PTX only.
// ---------------------------------------------------------------------------
__device__ __forceinline__ unsigned long long ffma2(unsigned long long a,
                                                    unsigned long long b,
                                                    unsigned long long c) {
    unsigned long long d;
    asm("fma.rn.f32x2 %0, %1, %2, %3;" : "=l"(d) : "l"(a), "l"(b), "l"(c));
    return d;
}
__device__ __forceinline__ unsigned long long pack2(float lo, float hi) {
    unsigned long long d;
    asm("mov.b64 %0, {%1, %2};" : "=l"(d) : "f"(lo), "f"(hi));
    return d;
}
__device__ __forceinline__ float2 unpack2(unsigned long long v) {
    float lo, hi;
    asm("mov.b64 {%0, %1}, %2;" : "=f"(lo), "=f"(hi) : "l"(v));
    return make_float2(lo, hi);
}
__device__ __forceinline__ float sigm(float x) {
    return __fdividef(1.f, 1.f + __expf(-x));
}

// ---------------------------------------------------------------------------
// One block per batch row b. 4 warps; warp w handles position-pairs
// pp = w + 4*j (j = 0..24), i.e. history positions h = 2*pp, 2*pp+1.
//
// Phase 0: dist features per position -> s_d   (position-per-thread)
// Phase 1: MLP partials. Lane k owns hidden unit k; 66 attn1 weights of
//          column k pre-packed as 32 x u64 (f32x2) in registers; products
//          broadcast via per-warp smem; per-lane (v_k, s_k) partials written
//          to s_vs as half2 (NO cross-lane reduction in the loop).
// Phase 2: per-position reduction over k (conflict-free LDS.128), masked exp,
//          block reduction, final sigmoid.
// ---------------------------------------------------------------------------
__global__ __launch_bounds__(THREADS, 3)
void nais_kernel(const int*   __restrict__ history,
                 const int*   __restrict__ target,
                 const int*   __restrict__ history_region,
                 const int*   __restrict__ target_region,
                 const float* __restrict__ lat_long,
                 const float* __restrict__ W_hist,
                 const float* __restrict__ W_tgt,
                 const float* __restrict__ W_reg,
                 const float* __restrict__ attn1_W,
                 const float* __restrict__ attn1_b,
                 const float* __restrict__ attn2_W,
                 const float* __restrict__ dist_W,
                 const float* __restrict__ dist_b,
                 float*       __restrict__ out)
{
    const int b    = blockIdx.x;
    const int tid  = threadIdx.x;
    const int w    = tid >> 5;
    const int lane = tid & 31;

    __shared__ __align__(16) float    s_pA[NW][64];
    __shared__ __align__(16) float    s_pB[NW][64];
    __shared__ __align__(16) unsigned s_vs[HH * VSTRIDE];  // half2(v_k, s_k)
    __shared__ __align__(16) float2   s_d[HH];             // dist features
    __shared__ float2 s_red[NW];

    // ---- per-lane MLP weights: column k of attn1_W, packed in (row,row+1) pairs
    unsigned long long wpair[32];
#pragma unroll
    for (int jj = 0; jj < 32; jj++) {
        wpair[jj] = pack2(attn1_W[(2 * jj) * 32 + lane],
                          attn1_W[(2 * jj + 1) * 32 + lane]);
    }
    const float wd0  = attn1_W[64 * 32 + lane];
    const float wd1  = attn1_W[65 * 32 + lane];
    const float bias = attn1_b[lane];
    const float w2k  = attn2_W[lane];

    const int tgt  = target[b];
    const int treg = target_region[b];
    const int base = b * HH;

    // target embedding values for this lane's element pair (2*lane, 2*lane+1)
    float t0, t1;
    if (lane < 16) {
        float2 t = *(const float2*)(W_tgt + (size_t)tgt * 32 + 2 * lane);
        t0 = t.x; t1 = t.y;
    } else {
        float2 t = *(const float2*)(W_reg + (size_t)treg * 32 + (2 * lane - 32));
        t0 = t.x; t1 = t.y;
    }

    // ================= Phase 0: dist features (position per thread) =========
    {
        const float dw00 = dist_W[0] * 100.f, dw01 = dist_W[1] * 100.f;
        const float dw10 = dist_W[2] * 100.f, dw11 = dist_W[3] * 100.f;
        const float db0  = dist_b[0],         db1  = dist_b[1];
        for (int p = tid; p < HH; p += THREADS) {
            float2 ll = *(const float2*)(lat_long + (size_t)(base + p) * 2);
            float d0 = sigm(fmaf(ll.x, dw00, fmaf(ll.y, dw10, db0)));
            float d1 = sigm(fmaf(ll.x, dw01, fmaf(ll.y, dw11, db1)));
            s_d[p] = make_float2(d0, d1);
        }
    }
    __syncthreads();

    // ================= Phase 1: MLP partials ================================
    auto ld_idx = [&](int j, int& iA, int& iB, int& rA, int& rB) {
        int jj = (j < PPW) ? j : (PPW - 1);   // clamp (prefetch overrun)
        int h  = 2 * (w + NW * jj);
        iA = history[base + h];          iB = history[base + h + 1];
        rA = history_region[base + h];   rB = history_region[base + h + 1];
    };
    auto ld_emb = [&](int iA, int iB, int rA, int rB, float2& a, float2& c) {
        const float *pa, *pb;
        if (lane < 16) {
            pa = W_hist + (size_t)iA * 32 + 2 * lane;
            pb = W_hist + (size_t)iB * 32 + 2 * lane;
        } else {
            pa = W_reg + (size_t)rA * 32 + (2 * lane - 32);
            pb = W_reg + (size_t)rB * 32 + (2 * lane - 32);
        }
        a = *(const float2*)pa;
        c = *(const float2*)pb;
    };

    // pipeline: embeddings resident 2 iterations ahead; indices 3 ahead
    int fA, fB, fRA, fRB;              // idx for pair j+2 (to issue its emb)
    {
        int cA, cB, cRA, cRB, nA, nB, nRA, nRB;
        ld_idx(0, cA, cB, cRA, cRB);
        ld_idx(1, nA, nB, nRA, nRB);
        ld_idx(2, fA, fB, fRA, fRB);
        ld_emb(cA, cB, cRA, cRB, *(float2*)&s_red, *(float2*)&s_red); // placeholder avoided below
        // (real prologue below — the line above is dead; kept simple:)
    }
    float2 eA, eB, e1A, e1B;
    {
        int cA, cB, cRA, cRB, nA, nB, nRA, nRB;
        ld_idx(0, cA, cB, cRA, cRB);
        ld_idx(1, nA, nB, nRA, nRB);
        ld_emb(cA, cB, cRA, cRB, eA, eB);
        ld_emb(nA, nB, nRA, nRB, e1A, e1B);
    }

#pragma unroll 2
    for (int j = 0; j < PPW; j++) {
        // issue embedding for pair j+2; fetch indices for pair j+3
        float2 e2A, e2B;
        ld_emb(fA, fB, fRA, fRB, e2A, e2B);
        int gA, gB, gRA, gRB;
        ld_idx(j + 3, gA, gB, gRA, gRB);

        const int h = 2 * (w + NW * j);

        // dist features for both positions: one broadcast LDS.128
        float4 dd = *(const float4*)&s_d[h];   // (dA0,dA1,dB0,dB1)

        // products p = h_emb * t_emb -> per-warp shared buffers
        float pA0 = eA.x * t0, pA1 = eA.y * t1;
        float pB0 = eB.x * t0, pB1 = eB.y * t1;
        *(float2*)&s_pA[w][2 * lane] = make_float2(pA0, pA1);
        *(float2*)&s_pB[w][2 * lane] = make_float2(pB0, pB1);
        __syncwarp();

        // hid_k = sum_i p_i * W1[i][k]  — 64 FFMA2, 32 broadcast LDS.128
        unsigned long long a0 = 0, a1 = 0, b0 = 0, b1 = 0;
        const ulonglong2* qA = (const ulonglong2*)s_pA[w];
        const ulonglong2* qB = (const ulonglong2*)s_pB[w];
#pragma unroll
        for (int i = 0; i < 16; i++) {
            ulonglong2 xa = qA[i];
            ulonglong2 xb = qB[i];
            a0 = ffma2(xa.x, wpair[2 * i],     a0);
            a1 = ffma2(xa.y, wpair[2 * i + 1], a1);
            b0 = ffma2(xb.x, wpair[2 * i],     b0);
            b1 = ffma2(xb.y, wpair[2 * i + 1], b1);
        }
        float2 fa0 = unpack2(a0), fa1 = unpack2(a1);
        float2 fb0 = unpack2(b0), fb1 = unpack2(b1);

        float hidA = fa0.x + fa0.y + fa1.x + fa1.y
                   + fmaf(dd.x, wd0, fmaf(dd.y, wd1, bias));
        float hidB = fb0.x + fb0.y + fb1.x + fb1.y
                   + fmaf(dd.z, wd0, fmaf(dd.w, wd1, bias));
        float vA = fmaxf(hidA, 0.f) * w2k;   // per-lane score partial
        float vB = fmaxf(hidB, 0.f) * w2k;
        float sA = pA0 + pA1;                // per-lane dot partial
        float sB = pB0 + pB1;

        // store per-lane partials as half2(v,s) — reduced in phase 2
        __half2 ha; ha.x = __float2half_rn(vA); ha.y = __float2half_rn(sA);
        __half2 hb; hb.x = __float2half_rn(vB); hb.y = __float2half_rn(sB);
        *(__half2*)&s_vs[h * VSTRIDE + lane]       = ha;
        *(__half2*)&s_vs[(h + 1) * VSTRIDE + lane] = hb;

        __syncwarp();   // product buffers free for next iteration

        // rotate pipeline
        eA = e1A; eB = e1B; e1A = e2A; e1B = e2B;
        fA = gA; fB = gB; fRA = gRA; fRB = gRB;
    }
    __syncthreads();

    // ================= Phase 2: per-position reduction + masked exp =========
    float se = 0.f, sp = 0.f;
    for (int p = tid; p < HH; p += THREADS) {
        const unsigned* row = s_vs + p * VSTRIDE;
        float sc = 0.f, dt = 0.f;
#pragma unroll
        for (int i = 0; i < 8; i++) {
            uint4 u = *(const uint4*)(row + 4 * i);
            float2 f0 = __half22float2(*(__half2*)&u.x);
            float2 f1 = __half22float2(*(__half2*)&u.y);
            float2 f2 = __half22float2(*(__half2*)&u.z);
            float2 f3 = __half22float2(*(__half2*)&u.w);
            sc += (f0.x + f1.x) + (f2.x + f3.x);
            dt += (f0.y + f1.y) + (f2.y + f3.y);
        }
        int hi = history[base + p];
        float e = (hi != tgt) ? __expf(sc) : 0.f;
        se += e;
        sp = fmaf(e, dt, sp);
    }
#pragma unroll
    for (int off = 16; off; off >>= 1) {
        se += __shfl_xor_sync(0xffffffffu, se, off);
        sp += __shfl_xor_sync(0xffffffffu, sp, off);
    }
    if (lane == 0) s_red[w] = make_float2(se, sp);
    __syncthreads();
    if (tid == 0) {
        float SE = 0.f, SP = 0.f;
#pragma unroll
        for (int i = 0; i < NW; i++) { SE += s_red[i].x; SP += s_red[i].y; }
        // attn_w = expA / sum^0.5 -> pred = SP / sqrt(SE)
        out[b] = sigm(SP * rsqrtf(SE));
    }
}

extern "C" void kernel_launch(void* const* d_in, const int* in_sizes, int n_in,
                              void* d_out, int out_size) {
    const int B = in_sizes[1];   // target is [B]
    nais_kernel<<<B, THREADS>>>(
        (const int*)  d_in[0],   // history [B,H]
        (const int*)  d_in[1],   // target [B]
        (const int*)  d_in[2],   // history_region [B,H]
        (const int*)  d_in[3],   // target_region [B]
        (const float*)d_in[4],   // target_lat_long [B,H,2]
        (const float*)d_in[5],   // W_hist
        (const float*)d_in[6],   // W_tgt
        (const float*)d_in[7],   // W_reg
        (const float*)d_in[8],   // attn1_W [66,32]
        (const float*)d_in[9],   // attn1_b [32]
        (const float*)d_in[10],  // attn2_W [32,1]
        (const float*)d_in[11],  // dist_W [2,2]
        (const float*)d_in[12],  // dist_b [2]
        (float*)d_out);
}

// round 4
// speedup vs baseline: 2.7344x; 1.6632x over previous
#include <cuda_runtime.h>
#include <cuda_bf16.h>
#include <cstdint>

#define HH      200
#define NWARP   7
#define THREADS 224

// per-warp A staging: tile0 = 32 rows x 128B (SW128-swizzled bf16, k 0..63)
//                     tile1 = 32 rows x 48B  (k 64..79: dist, const-1, pad)
#define T0_BYTES (32 * 128)
#define T1_BYTES (32 * 48)
#define AW_BYTES (T0_BYTES + T1_BYTES)

// B weight matrix in smem: [40 n-rows][88 k bf16] (stride 176B, conflict-free LDSM)
#define WB_STRIDE 88

__device__ __forceinline__ uint32_t cvt2bf(float hi, float lo) {
    uint32_t r;
    asm("cvt.rn.bf16x2.f32 %0, %1, %2;" : "=r"(r) : "f"(hi), "f"(lo));
    return r;
}
__device__ __forceinline__ float sigm(float x) {
    return __fdividef(1.f, 1.f + __expf(-x));
}
__device__ __forceinline__ void ldsm_x4(uint32_t addr, uint32_t& r0, uint32_t& r1,
                                        uint32_t& r2, uint32_t& r3) {
    asm volatile("ldmatrix.sync.aligned.m8n8.x4.shared.b16 {%0,%1,%2,%3}, [%4];"
                 : "=r"(r0), "=r"(r1), "=r"(r2), "=r"(r3) : "r"(addr));
}
__device__ __forceinline__ void ldsm_x2(uint32_t addr, uint32_t& r0, uint32_t& r1) {
    asm volatile("ldmatrix.sync.aligned.m8n8.x2.shared.b16 {%0,%1}, [%2];"
                 : "=r"(r0), "=r"(r1) : "r"(addr));
}
__device__ __forceinline__ void mma16816(float* d, const uint32_t* a,
                                         uint32_t b0, uint32_t b1) {
    asm volatile(
        "mma.sync.aligned.m16n8k16.row.col.f32.bf16.bf16.f32 "
        "{%0,%1,%2,%3}, {%4,%5,%6,%7}, {%8,%9}, {%0,%1,%2,%3};"
        : "+f"(d[0]), "+f"(d[1]), "+f"(d[2]), "+f"(d[3])
        : "r"(a[0]), "r"(a[1]), "r"(a[2]), "r"(a[3]), "r"(b0), "r"(b1));
}

// ---------------------------------------------------------------------------
// One block per batch row. 7 warps; warp w owns positions [32w, 32w+32)
// (padded past 200; pad rows masked in epilogue).
//
// MMA: D[200pad, 40] = A[200pad, 80] x B[80, 40]   (bf16 in, fp32 acc)
//   A rows = positions. k 0..63 = raw h_emb, k 64,65 = dist feats,
//   k 66 = 1.0 (bias feature), k 67..79 = 0.
//   B[k][n] (n<32) = t_k * attn1_W[k][n] (k<64); W1[64..65][n]; attn1_b[n](k=66)
//   B[k][32]       = t_k (k<64) -> D[:,32] = dot(h_emb, t_emb)
// ---------------------------------------------------------------------------
__global__ __launch_bounds__(THREADS, 2)
void nais_kernel(const int*   __restrict__ history,
                 const int*   __restrict__ target,
                 const int*   __restrict__ history_region,
                 const int*   __restrict__ target_region,
                 const float* __restrict__ lat_long,
                 const float* __restrict__ W_hist,
                 const float* __restrict__ W_tgt,
                 const float* __restrict__ W_reg,
                 const float* __restrict__ attn1_W,
                 const float* __restrict__ attn1_b,
                 const float* __restrict__ attn2_W,
                 const float* __restrict__ dist_W,
                 const float* __restrict__ dist_b,
                 float*       __restrict__ out)
{
    __shared__ __align__(16) unsigned char s_A[NWARP * AW_BYTES];
    __shared__ __align__(16) __nv_bfloat16 s_W[40 * WB_STRIDE];
    __shared__ float  s_t[64];
    __shared__ float2 s_red[NWARP];

    const int b    = blockIdx.x;
    const int tid  = threadIdx.x;
    const int w    = tid >> 5;
    const int lane = tid & 31;
    const int gid  = lane >> 2;
    const int tig  = lane & 3;
    const int base = b * HH;
    const int tgt  = target[b];
    const int tb   = 32 * w;

    unsigned char* myA = s_A + w * AW_BYTES;

    // ---- target embedding -> s_t[64]
    if (tid < 32) {
        float2 t;
        if (tid < 16) t = *(const float2*)(W_tgt + (size_t)tgt * 32 + 2 * tid);
        else {
            int tr = target_region[b];
            t = *(const float2*)(W_reg + (size_t)tr * 32 + (2 * tid - 32));
        }
        s_t[2 * tid]     = t.x;
        s_t[2 * tid + 1] = t.y;
    }

    // ---- tile1 init: row = lane. word1 = (k66=1.0, k67=0); rest 0
    {
        uint4* r = (uint4*)(myA + T0_BYTES + lane * 48);
        r[0] = make_uint4(0u, 0x00003F80u, 0u, 0u);
        r[1] = make_uint4(0u, 0u, 0u, 0u);
        r[2] = make_uint4(0u, 0u, 0u, 0u);
    }

    // ---- per-warp position indices (clamped against OOB on last tile)
    const int posl = min(tb + lane, HH - 1);
    const int idxv = history[base + posl];
    const int regv = history_region[base + posl];

    __syncthreads();   // s_t visible

    // ---- fill B weights (1760 bf16x2 words across 220 threads)
    {
        int w0 = tid * 8;
        if (w0 < 40 * (WB_STRIDE / 2)) {
#pragma unroll
            for (int u = 0; u < 8; u++) {
                int wd = w0 + u;
                int n  = wd / (WB_STRIDE / 2);
                int kp = wd % (WB_STRIDE / 2);
                int k0 = 2 * kp, k1 = 2 * kp + 1;
                auto wv = [&](int k) -> float {
                    if (k >= 80 || n >= 40) return 0.f;
                    if (n < 32) {
                        if (k < 64) return s_t[k] * attn1_W[k * 32 + n];
                        if (k < 66) return attn1_W[k * 32 + n];
                        if (k == 66) return attn1_b[n];
                        return 0.f;
                    }
                    if (n == 32) return (k < 64) ? s_t[k] : 0.f;
                    return 0.f;
                };
                ((uint32_t*)s_W)[wd] = cvt2bf(wv(k1), wv(k0));
            }
        }
    }

    // ---- dist features: lane = local position; word0 of tile1 row
    {
        const float dw00 = dist_W[0] * 100.f, dw01 = dist_W[1] * 100.f;
        const float dw10 = dist_W[2] * 100.f, dw11 = dist_W[3] * 100.f;
        float2 ll = *(const float2*)(lat_long + (size_t)(base + posl) * 2);
        float d0 = sigm(fmaf(ll.x, dw00, fmaf(ll.y, dw10, dist_b[0])));
        float d1 = sigm(fmaf(ll.x, dw01, fmaf(ll.y, dw11, dist_b[1])));
        *(uint32_t*)(myA + T0_BYTES + lane * 48) = cvt2bf(d1, d0);
    }

    // ---- gather + cvt + swizzled store (4 lanes cooperate per position row)
    {
        const int c    = lane & 7;     // fp32 16B-chunk within the 128B table row
        const int rsel = lane >> 3;    // which of 4 rows this lane serves
#pragma unroll
        for (int q = 0; q < 8; q++) {
            int prow = 4 * q + rsel;   // local position 0..31
            int ii = __shfl_sync(0xffffffffu, idxv, prow);
            int rr = __shfl_sync(0xffffffffu, regv, prow);
            float4 eh = *(const float4*)(W_hist + (size_t)ii * 32 + 4 * c);
            float4 er = *(const float4*)(W_reg  + (size_t)rr * 32 + 4 * c);
            uint2 hv = make_uint2(cvt2bf(eh.y, eh.x), cvt2bf(eh.w, eh.z));
            uint2 rv = make_uint2(cvt2bf(er.y, er.x), cvt2bf(er.w, er.z));
            // bf16 dest: hist -> 16B-chunks 0..3, reg -> 4..7 (SW128 xor row&7)
            uint32_t half8 = (c & 1) << 3;
            uint32_t a0 = prow * 128 + ((((c >> 1)    ) ^ (prow & 7)) << 4) + half8;
            uint32_t a1 = prow * 128 + ((((c >> 1) + 4) ^ (prow & 7)) << 4) + half8;
            *(uint2*)(myA + a0) = hv;
            *(uint2*)(myA + a1) = rv;
        }
    }
    __syncthreads();   // A tiles + B weights all visible

    // ---- MMA: 2 m-tiles x 5 n-tiles x 5 k-steps
    float d[2][5][4];
#pragma unroll
    for (int mt = 0; mt < 2; mt++)
#pragma unroll
        for (int nn = 0; nn < 5; nn++)
#pragma unroll
            for (int i = 0; i < 4; i++) d[mt][nn][i] = 0.f;

    const uint32_t aT0 = (uint32_t)__cvta_generic_to_shared(myA);
    const uint32_t aT1 = aT0 + T0_BYTES;
    const uint32_t wB  = (uint32_t)__cvta_generic_to_shared(s_W);

#pragma unroll
    for (int kk = 0; kk < 5; kk++) {
        uint32_t a[2][4];
#pragma unroll
        for (int mt = 0; mt < 2; mt++) {
            int row = 16 * mt + (lane & 15);
            uint32_t addr;
            if (kk < 4) {
                int chunk = 2 * kk + (lane >> 4);
                addr = aT0 + row * 128 + ((chunk ^ (row & 7)) << 4);
            } else {
                addr = aT1 + row * 48 + ((lane >> 4) << 4);
            }
            ldsm_x4(addr, a[mt][0], a[mt][1], a[mt][2], a[mt][3]);
        }
#pragma unroll
        for (int nn = 0; nn < 5; nn++) {
            uint32_t b0, b1;
            int nrow = 8 * nn + (lane & 7);
            uint32_t baddr = wB + nrow * (WB_STRIDE * 2) + ((lane & 8) ? 16 : 0)
                           + kk * 32;
            ldsm_x2(baddr, b0, b1);
            mma16816(d[0][nn], a[0], b0, b1);
            mma16816(d[1][nn], a[1], b0, b1);
        }
    }

    // ---- epilogue: relu(hid) . w2, dot from col 32, masked exp, reduce
    float v00 = 0.f, v01 = 0.f, v10 = 0.f, v11 = 0.f;
#pragma unroll
    for (int nn = 0; nn < 4; nn++) {
        float w2a = attn2_W[8 * nn + 2 * tig];
        float w2b = attn2_W[8 * nn + 2 * tig + 1];
        v00 = fmaf(fmaxf(d[0][nn][0], 0.f), w2a, fmaf(fmaxf(d[0][nn][1], 0.f), w2b, v00));
        v01 = fmaf(fmaxf(d[0][nn][2], 0.f), w2a, fmaf(fmaxf(d[0][nn][3], 0.f), w2b, v01));
        v10 = fmaf(fmaxf(d[1][nn][0], 0.f), w2a, fmaf(fmaxf(d[1][nn][1], 0.f), w2b, v10));
        v11 = fmaf(fmaxf(d[1][nn][2], 0.f), w2a, fmaf(fmaxf(d[1][nn][3], 0.f), w2b, v11));
    }
#pragma unroll
    for (int off = 1; off <= 2; off <<= 1) {
        v00 += __shfl_xor_sync(0xffffffffu, v00, off);
        v01 += __shfl_xor_sync(0xffffffffu, v01, off);
        v10 += __shfl_xor_sync(0xffffffffu, v10, off);
        v11 += __shfl_xor_sync(0xffffffffu, v11, off);
    }
    // dots live in tig==0 lanes at nn=4 (col 32): c0 = row gid, c2 = row gid+8
    int srcl = lane & ~3;
    float q00 = __shfl_sync(0xffffffffu, d[0][4][0], srcl);
    float q01 = __shfl_sync(0xffffffffu, d[0][4][2], srcl);
    float q10 = __shfl_sync(0xffffffffu, d[1][4][0], srcl);
    float q11 = __shfl_sync(0xffffffffu, d[1][4][2], srcl);

    float score = (tig == 0) ? v00 : (tig == 1) ? v01 : (tig == 2) ? v10 : v11;
    float dotv  = (tig == 0) ? q00 : (tig == 1) ? q01 : (tig == 2) ? q10 : q11;

    int posl2 = gid + 8 * tig;                       // local row this lane owns
    int idx   = __shfl_sync(0xffffffffu, idxv, posl2);
    bool ok   = (idx != tgt) && (tb + posl2 < HH);
    float e   = ok ? __expf(score) : 0.f;
    float se  = e;
    float sp  = e * dotv;
#pragma unroll
    for (int off = 16; off; off >>= 1) {
        se += __shfl_xor_sync(0xffffffffu, se, off);
        sp += __shfl_xor_sync(0xffffffffu, sp, off);
    }
    if (lane == 0) s_red[w] = make_float2(se, sp);
    __syncthreads();
    if (tid == 0) {
        float SE = 0.f, SP = 0.f;
#pragma unroll
        for (int i = 0; i < NWARP; i++) { SE += s_red[i].x; SP += s_red[i].y; }
        out[b] = sigm(SP * rsqrtf(SE));   // BETA=0.5: pred = SP / sqrt(SE)
    }
}

extern "C" void kernel_launch(void* const* d_in, const int* in_sizes, int n_in,
                              void* d_out, int out_size) {
    const int B = in_sizes[1];   // target is [B]
    nais_kernel<<<B, THREADS>>>(
        (const int*)  d_in[0],   // history [B,H]
        (const int*)  d_in[1],   // target [B]
        (const int*)  d_in[2],   // history_region [B,H]
        (const int*)  d_in[3],   // target_region [B]
        (const float*)d_in[4],   // target_lat_long [B,H,2]
        (const float*)d_in[5],   // W_hist
        (const float*)d_in[6],   // W_tgt
        (const float*)d_in[7],   // W_reg
        (const float*)d_in[8],   // attn1_W [66,32]
        (const float*)d_in[9],   // attn1_b [32]
        (const float*)d_in[10],  // attn2_W [32,1]
        (const float*)d_in[11],  // dist_W [2,2]
        (const float*)d_in[12],  // dist_b [2]
        (float*)d_out);
}

// round 5
// speedup vs baseline: 4.1538x; 1.5191x over previous
#include <cuda_runtime.h>
#include <cuda_bf16.h>
#include <cstdint>

#define HH      200
#define NWARP   7
#define THREADS 224

// per-warp A staging: tile0 = 32 rows x 128B (SW128-swizzled bf16, k 0..63)
//                     tile1 = 32 rows x 48B  (k 64..79: dist, const-1, pad)
#define T0_BYTES (32 * 128)
#define T1_BYTES (32 * 48)
#define AW_BYTES (T0_BYTES + T1_BYTES)

// B weight matrix in smem: [40 n-rows][88 k bf16] (stride 176B, conflict-free LDSM)
#define WB_STRIDE 88

__device__ __forceinline__ uint32_t cvt2bf(float hi, float lo) {
    uint32_t r;
    asm("cvt.rn.bf16x2.f32 %0, %1, %2;" : "=r"(r) : "f"(hi), "f"(lo));
    return r;
}
__device__ __forceinline__ float sigm(float x) {
    return __fdividef(1.f, 1.f + __expf(-x));
}
__device__ __forceinline__ void ldsm_x4(uint32_t addr, uint32_t& r0, uint32_t& r1,
                                        uint32_t& r2, uint32_t& r3) {
    asm volatile("ldmatrix.sync.aligned.m8n8.x4.shared.b16 {%0,%1,%2,%3}, [%4];"
                 : "=r"(r0), "=r"(r1), "=r"(r2), "=r"(r3) : "r"(addr));
}
__device__ __forceinline__ void ldsm_x2(uint32_t addr, uint32_t& r0, uint32_t& r1) {
    asm volatile("ldmatrix.sync.aligned.m8n8.x2.shared.b16 {%0,%1}, [%2];"
                 : "=r"(r0), "=r"(r1) : "r"(addr));
}
__device__ __forceinline__ void mma16816(float* d, const uint32_t* a,
                                         uint32_t b0, uint32_t b1) {
    asm volatile(
        "mma.sync.aligned.m16n8k16.row.col.f32.bf16.bf16.f32 "
        "{%0,%1,%2,%3}, {%4,%5,%6,%7}, {%8,%9}, {%0,%1,%2,%3};"
        : "+f"(d[0]), "+f"(d[1]), "+f"(d[2]), "+f"(d[3])
        : "r"(a[0]), "r"(a[1]), "r"(a[2]), "r"(a[3]), "r"(b0), "r"(b1));
}

// ---------------------------------------------------------------------------
// One block per batch row. 7 warps; warp w owns positions [32w, 32w+32).
//
// MMA: D[200pad, 40] = A[200pad, 80] x B[80, 40]   (bf16 in, fp32 acc)
//   A rows = positions. k 0..63 = raw h_emb, k 64,65 = dist feats,
//   k 66 = 1.0 (bias feature), k 67..79 = 0.
//   B[k][n] (n<32) = t_k * attn1_W[k][n] (k<64); W1[64..65][n]; attn1_b[n](k=66)
//   B[k][32]       = t_k (k<64) -> D[:,32] = dot(h_emb, t_emb)
//
// ONE barrier total: all gmem loads issue up front; B-fill reads its target-
// embedding scalars straight from gmem (no shared staging, no extra barrier).
// ---------------------------------------------------------------------------
__global__ __launch_bounds__(THREADS, 3)
void nais_kernel(const int*   __restrict__ history,
                 const int*   __restrict__ target,
                 const int*   __restrict__ history_region,
                 const int*   __restrict__ target_region,
                 const float* __restrict__ lat_long,
                 const float* __restrict__ W_hist,
                 const float* __restrict__ W_tgt,
                 const float* __restrict__ W_reg,
                 const float* __restrict__ attn1_W,
                 const float* __restrict__ attn1_b,
                 const float* __restrict__ attn2_W,
                 const float* __restrict__ dist_W,
                 const float* __restrict__ dist_b,
                 float*       __restrict__ out)
{
    __shared__ __align__(16) unsigned char s_A[NWARP * AW_BYTES];
    __shared__ __align__(16) __nv_bfloat16 s_W[40 * WB_STRIDE];
    __shared__ float2 s_red[NWARP];

    const int b    = blockIdx.x;
    const int tid  = threadIdx.x;
    const int w    = tid >> 5;
    const int lane = tid & 31;
    const int gid  = lane >> 2;
    const int tig  = lane & 3;
    const int base = b * HH;
    const int tgt  = target[b];
    const int treg = target_region[b];
    const int tb   = 32 * w;

    unsigned char* myA = s_A + w * AW_BYTES;

    // ---- per-warp position indices + lat_long (issued first; longest chains)
    const int posl = min(tb + lane, HH - 1);
    const int idxv = history[base + posl];
    const int regv = history_region[base + posl];
    float2 ll = *(const float2*)(lat_long + (size_t)(base + posl) * 2);

    // ---- epilogue weights (hoisted; independent)
    float2 w2v[4];
#pragma unroll
    for (int nn = 0; nn < 4; nn++)
        w2v[nn] = *(const float2*)(attn2_W + 8 * nn + 2 * tig);

    // ---- B-fill: thread = (n-group of 8, k-pair kp). 6 LDGs, all independent.
    //      word(n, kp) = bf16x2( t_{k1}*W[k1][n], t_{k0}*W[k0][n] )
    float bw[8], cw[8];
    float t0 = 0.f, t1 = 0.f;
    int   kp = 0, n0g = 0;
    if (tid < 220) {
        kp  = tid % 44;
        n0g = (tid / 44) * 8;
        const int k0 = 2 * kp, k1 = k0 + 1;
#pragma unroll
        for (int u = 0; u < 8; u++) { bw[u] = 0.f; cw[u] = 0.f; }
        const bool g4 = (n0g == 32);          // n 32..39: dot column + zero pad
        if (g4) {
            bw[0] = 1.f; cw[0] = 1.f;         // n=32 gets (t_k0, t_k1)
            if (k0 < 64) {
                t0 = (k0 < 32) ? W_tgt[(size_t)tgt * 32 + k0]
                               : W_reg[(size_t)treg * 32 + k0 - 32];
                t1 = (k1 < 32) ? W_tgt[(size_t)tgt * 32 + k1]
                               : W_reg[(size_t)treg * 32 + k1 - 32];
            }
        } else if (k0 < 64) {
            float4 x0 = *(const float4*)(attn1_W + k0 * 32 + n0g);
            float4 x1 = *(const float4*)(attn1_W + k0 * 32 + n0g + 4);
            float4 y0 = *(const float4*)(attn1_W + k1 * 32 + n0g);
            float4 y1 = *(const float4*)(attn1_W + k1 * 32 + n0g + 4);
            bw[0]=x0.x; bw[1]=x0.y; bw[2]=x0.z; bw[3]=x0.w;
            bw[4]=x1.x; bw[5]=x1.y; bw[6]=x1.z; bw[7]=x1.w;
            cw[0]=y0.x; cw[1]=y0.y; cw[2]=y0.z; cw[3]=y0.w;
            cw[4]=y1.x; cw[5]=y1.y; cw[6]=y1.z; cw[7]=y1.w;
            t0 = (k0 < 32) ? W_tgt[(size_t)tgt * 32 + k0]
                           : W_reg[(size_t)treg * 32 + k0 - 32];
            t1 = (k1 < 32) ? W_tgt[(size_t)tgt * 32 + k1]
                           : W_reg[(size_t)treg * 32 + k1 - 32];
        } else if (k0 == 64) {                // dist-feature weight rows
            float4 x0 = *(const float4*)(attn1_W + 64 * 32 + n0g);
            float4 x1 = *(const float4*)(attn1_W + 64 * 32 + n0g + 4);
            float4 y0 = *(const float4*)(attn1_W + 65 * 32 + n0g);
            float4 y1 = *(const float4*)(attn1_W + 65 * 32 + n0g + 4);
            bw[0]=x0.x; bw[1]=x0.y; bw[2]=x0.z; bw[3]=x0.w;
            bw[4]=x1.x; bw[5]=x1.y; bw[6]=x1.z; bw[7]=x1.w;
            cw[0]=y0.x; cw[1]=y0.y; cw[2]=y0.z; cw[3]=y0.w;
            cw[4]=y1.x; cw[5]=y1.y; cw[6]=y1.z; cw[7]=y1.w;
            t0 = 1.f; t1 = 1.f;
        } else if (k0 == 66) {                // bias feature row
            float4 x0 = *(const float4*)(attn1_b + n0g);
            float4 x1 = *(const float4*)(attn1_b + n0g + 4);
            bw[0]=x0.x; bw[1]=x0.y; bw[2]=x0.z; bw[3]=x0.w;
            bw[4]=x1.x; bw[5]=x1.y; bw[6]=x1.z; bw[7]=x1.w;
            t0 = 1.f;                          // t1=0 -> k67 column zero
        }
        // kp >= 34 (non-g4): all zero
    }

    // ---- tile1 init: row = lane. word1 = (k66=1.0, k67=0); rest 0
    {
        uint4* r = (uint4*)(myA + T0_BYTES + lane * 48);
        r[0] = make_uint4(0u, 0x00003F80u, 0u, 0u);
        r[1] = make_uint4(0u, 0u, 0u, 0u);
        r[2] = make_uint4(0u, 0u, 0u, 0u);
    }

    // ---- dist features -> tile1 word0 (independent of everything above)
    {
        const float dw00 = dist_W[0] * 100.f, dw01 = dist_W[1] * 100.f;
        const float dw10 = dist_W[2] * 100.f, dw11 = dist_W[3] * 100.f;
        float d0 = sigm(fmaf(ll.x, dw00, fmaf(ll.y, dw10, dist_b[0])));
        float d1 = sigm(fmaf(ll.x, dw01, fmaf(ll.y, dw11, dist_b[1])));
        *(uint32_t*)(myA + T0_BYTES + lane * 48) = cvt2bf(d1, d0);
    }

    // ---- B-fill stores (after loads land)
    if (tid < 220) {
#pragma unroll
        for (int u = 0; u < 8; u++) {
            ((uint32_t*)s_W)[(n0g + u) * (WB_STRIDE / 2) + kp] =
                cvt2bf(t1 * cw[u], t0 * bw[u]);
        }
    }

    // ---- gather + cvt + swizzled store (4 lanes cooperate per position row)
    {
        const int c    = lane & 7;     // fp32 16B-chunk within the 128B table row
        const int rsel = lane >> 3;    // which of 4 rows this lane serves
#pragma unroll
        for (int q = 0; q < 8; q++) {
            int prow = 4 * q + rsel;   // local position 0..31
            int ii = __shfl_sync(0xffffffffu, idxv, prow);
            int rr = __shfl_sync(0xffffffffu, regv, prow);
            float4 eh = *(const float4*)(W_hist + (size_t)ii * 32 + 4 * c);
            float4 er = *(const float4*)(W_reg  + (size_t)rr * 32 + 4 * c);
            uint2 hv = make_uint2(cvt2bf(eh.y, eh.x), cvt2bf(eh.w, eh.z));
            uint2 rv = make_uint2(cvt2bf(er.y, er.x), cvt2bf(er.w, er.z));
            // bf16 dest: hist -> 16B-chunks 0..3, reg -> 4..7 (SW128 xor row&7)
            uint32_t half8 = (c & 1) << 3;
            uint32_t a0 = prow * 128 + ((((c >> 1)    ) ^ (prow & 7)) << 4) + half8;
            uint32_t a1 = prow * 128 + ((((c >> 1) + 4) ^ (prow & 7)) << 4) + half8;
            *(uint2*)(myA + a0) = hv;
            *(uint2*)(myA + a1) = rv;
        }
    }
    __syncthreads();   // the ONLY barrier: A tiles + B weights visible

    // ---- MMA: 2 m-tiles x 5 n-tiles x 5 k-steps
    float d[2][5][4];
#pragma unroll
    for (int mt = 0; mt < 2; mt++)
#pragma unroll
        for (int nn = 0; nn < 5; nn++)
#pragma unroll
            for (int i = 0; i < 4; i++) d[mt][nn][i] = 0.f;

    const uint32_t aT0 = (uint32_t)__cvta_generic_to_shared(myA);
    const uint32_t aT1 = aT0 + T0_BYTES;
    const uint32_t wB  = (uint32_t)__cvta_generic_to_shared(s_W);

#pragma unroll
    for (int kk = 0; kk < 5; kk++) {
        uint32_t a[2][4];
#pragma unroll
        for (int mt = 0; mt < 2; mt++) {
            int row = 16 * mt + (lane & 15);
            uint32_t addr;
            if (kk < 4) {
                int chunk = 2 * kk + (lane >> 4);
                addr = aT0 + row * 128 + ((chunk ^ (row & 7)) << 4);
            } else {
                addr = aT1 + row * 48 + ((lane >> 4) << 4);
            }
            ldsm_x4(addr, a[mt][0], a[mt][1], a[mt][2], a[mt][3]);
        }
#pragma unroll
        for (int nn = 0; nn < 5; nn++) {
            uint32_t b0, b1;
            int nrow = 8 * nn + (lane & 7);
            uint32_t baddr = wB + nrow * (WB_STRIDE * 2) + ((lane & 8) ? 16 : 0)
                           + kk * 32;
            ldsm_x2(baddr, b0, b1);
            mma16816(d[0][nn], a[0], b0, b1);
            mma16816(d[1][nn], a[1], b0, b1);
        }
    }

    // ---- epilogue: relu(hid) . w2, dot from col 32, masked exp, reduce
    float v00 = 0.f, v01 = 0.f, v10 = 0.f, v11 = 0.f;
#pragma unroll
    for (int nn = 0; nn < 4; nn++) {
        float w2a = w2v[nn].x;
        float w2b = w2v[nn].y;
        v00 = fmaf(fmaxf(d[0][nn][0], 0.f), w2a, fmaf(fmaxf(d[0][nn][1], 0.f), w2b, v00));
        v01 = fmaf(fmaxf(d[0][nn][2], 0.f), w2a, fmaf(fmaxf(d[0][nn][3], 0.f), w2b, v01));
        v10 = fmaf(fmaxf(d[1][nn][0], 0.f), w2a, fmaf(fmaxf(d[1][nn][1], 0.f), w2b, v10));
        v11 = fmaf(fmaxf(d[1][nn][2], 0.f), w2a, fmaf(fmaxf(d[1][nn][3], 0.f), w2b, v11));
    }
#pragma unroll
    for (int off = 1; off <= 2; off <<= 1) {
        v00 += __shfl_xor_sync(0xffffffffu, v00, off);
        v01 += __shfl_xor_sync(0xffffffffu, v01, off);
        v10 += __shfl_xor_sync(0xffffffffu, v10, off);
        v11 += __shfl_xor_sync(0xffffffffu, v11, off);
    }
    // dots live in tig==0 lanes at nn=4 (col 32): c0 = row gid, c2 = row gid+8
    int srcl = lane & ~3;
    float q00 = __shfl_sync(0xffffffffu, d[0][4][0], srcl);
    float q01 = __shfl_sync(0xffffffffu, d[0][4][2], srcl);
    float q10 = __shfl_sync(0xffffffffu, d[1][4][0], srcl);
    float q11 = __shfl_sync(0xffffffffu, d[1][4][2], srcl);

    float score = (tig == 0) ? v00 : (tig == 1) ? v01 : (tig == 2) ? v10 : v11;
    float dotv  = (tig == 0) ? q00 : (tig == 1) ? q01 : (tig == 2) ? q10 : q11;

    int posl2 = gid + 8 * tig;                       // local row this lane owns
    int idx   = __shfl_sync(0xffffffffu, idxv, posl2);
    bool ok   = (idx != tgt) && (tb + posl2 < HH);
    float e   = ok ? __expf(score) : 0.f;
    float se  = e;
    float sp  = e * dotv;
#pragma unroll
    for (int off = 16; off; off >>= 1) {
        se += __shfl_xor_sync(0xffffffffu, se, off);
        sp += __shfl_xor_sync(0xffffffffu, sp, off);
    }
    if (lane == 0) s_red[w] = make_float2(se, sp);
    __syncthreads();
    if (tid == 0) {
        float SE = 0.f, SP = 0.f;
#pragma unroll
        for (int i = 0; i < NWARP; i++) { SE += s_red[i].x; SP += s_red[i].y; }
        out[b] = sigm(SP * rsqrtf(SE));   // BETA=0.5: pred = SP / sqrt(SE)
    }
}

extern "C" void kernel_launch(void* const* d_in, const int* in_sizes, int n_in,
                              void* d_out, int out_size) {
    const int B = in_sizes[1];   // target is [B]
    nais_kernel<<<B, THREADS>>>(
        (const int*)  d_in[0],   // history [B,H]
        (const int*)  d_in[1],   // target [B]
        (const int*)  d_in[2],   // history_region [B,H]
        (const int*)  d_in[3],   // target_region [B]
        (const float*)d_in[4],   // target_lat_long [B,H,2]
        (const float*)d_in[5],   // W_hist
        (const float*)d_in[6],   // W_tgt
        (const float*)d_in[7],   // W_reg
        (const float*)d_in[8],   // attn1_W [66,32]
        (const float*)d_in[9],   // attn1_b [32]
        (const float*)d_in[10],  // attn2_W [32,1]
        (const float*)d_in[11],  // dist_W [2,2]
        (const float*)d_in[12],  // dist_b [2]
        (float*)d_out);
}

// round 6
// speedup vs baseline: 4.1562x; 1.0006x over previous
#include <cuda_runtime.h>
#include <cuda_bf16.h>
#include <cstdint>

#define HH      200
#define NWARP   7
#define THREADS 224

// per-warp A staging: tile0 = 32 rows x 128B (SW128-swizzled bf16, k 0..63)
//                     tile1 = 32 rows x 48B  (k 64..79: dist, const-1, pad)
#define T0_BYTES (32 * 128)
#define T1_BYTES (32 * 48)
#define AW_BYTES (T0_BYTES + T1_BYTES)

// B weight matrix in smem: [40 n-rows][88 k bf16] (stride 176B, conflict-free LDSM)
#define WB_STRIDE 88

__device__ __forceinline__ uint32_t cvt2bf(float hi, float lo) {
    uint32_t r;
    asm("cvt.rn.bf16x2.f32 %0, %1, %2;" : "=r"(r) : "f"(hi), "f"(lo));
    return r;
}
__device__ __forceinline__ float sigm(float x) {
    return __fdividef(1.f, 1.f + __expf(-x));
}
__device__ __forceinline__ void ldsm_x4(uint32_t addr, uint32_t& r0, uint32_t& r1,
                                        uint32_t& r2, uint32_t& r3) {
    asm volatile("ldmatrix.sync.aligned.m8n8.x4.shared.b16 {%0,%1,%2,%3}, [%4];"
                 : "=r"(r0), "=r"(r1), "=r"(r2), "=r"(r3) : "r"(addr));
}
__device__ __forceinline__ void ldsm_x2(uint32_t addr, uint32_t& r0, uint32_t& r1) {
    asm volatile("ldmatrix.sync.aligned.m8n8.x2.shared.b16 {%0,%1}, [%2];"
                 : "=r"(r0), "=r"(r1) : "r"(addr));
}
__device__ __forceinline__ void mma16816(float* d, const uint32_t* a,
                                         uint32_t b0, uint32_t b1) {
    asm volatile(
        "mma.sync.aligned.m16n8k16.row.col.f32.bf16.bf16.f32 "
        "{%0,%1,%2,%3}, {%4,%5,%6,%7}, {%8,%9}, {%0,%1,%2,%3};"
        : "+f"(d[0]), "+f"(d[1]), "+f"(d[2]), "+f"(d[3])
        : "r"(a[0]), "r"(a[1]), "r"(a[2]), "r"(a[3]), "r"(b0), "r"(b1));
}

// ---------------------------------------------------------------------------
// One block per batch row. 7 warps; warp w owns positions [32w, 32w+32).
//
// MMA: D[200pad, 40] = A[200pad, 80] x B[80, 40]   (bf16 in, fp32 acc)
//   A rows = positions. k 0..63 = raw h_emb, k 64,65 = dist feats,
//   k 66 = 1.0 (bias feature), k 67..79 = 0.
//   B[k][n] (n<32) = t_k * attn1_W[k][n] (k<64); W1[64..65][n]; attn1_b[n](k=66)
//   B[k][32]       = t_k (k<64) -> D[:,32] = dot(h_emb, t_emb)
//
// ONE barrier total: all gmem loads issue up front; B-fill reads its target-
// embedding scalars straight from gmem (no shared staging, no extra barrier).
// ---------------------------------------------------------------------------
__global__ __launch_bounds__(THREADS, 3)
void nais_kernel(const int*   __restrict__ history,
                 const int*   __restrict__ target,
                 const int*   __restrict__ history_region,
                 const int*   __restrict__ target_region,
                 const float* __restrict__ lat_long,
                 const float* __restrict__ W_hist,
                 const float* __restrict__ W_tgt,
                 const float* __restrict__ W_reg,
                 const float* __restrict__ attn1_W,
                 const float* __restrict__ attn1_b,
                 const float* __restrict__ attn2_W,
                 const float* __restrict__ dist_W,
                 const float* __restrict__ dist_b,
                 float*       __restrict__ out)
{
    __shared__ __align__(16) unsigned char s_A[NWARP * AW_BYTES];
    __shared__ __align__(16) __nv_bfloat16 s_W[40 * WB_STRIDE];
    __shared__ float2 s_red[NWARP];

    const int b    = blockIdx.x;
    const int tid  = threadIdx.x;
    const int w    = tid >> 5;
    const int lane = tid & 31;
    const int gid  = lane >> 2;
    const int tig  = lane & 3;
    const int base = b * HH;
    const int tgt  = target[b];
    const int treg = target_region[b];
    const int tb   = 32 * w;

    unsigned char* myA = s_A + w * AW_BYTES;

    // ---- per-warp position indices + lat_long (issued first; longest chains)
    const int posl = min(tb + lane, HH - 1);
    const int idxv = history[base + posl];
    const int regv = history_region[base + posl];
    float2 ll = *(const float2*)(lat_long + (size_t)(base + posl) * 2);

    // ---- epilogue weights (hoisted; independent)
    float2 w2v[4];
#pragma unroll
    for (int nn = 0; nn < 4; nn++)
        w2v[nn] = *(const float2*)(attn2_W + 8 * nn + 2 * tig);

    // ---- B-fill: thread = (n-group of 8, k-pair kp). 6 LDGs, all independent.
    //      word(n, kp) = bf16x2( t_{k1}*W[k1][n], t_{k0}*W[k0][n] )
    float bw[8], cw[8];
    float t0 = 0.f, t1 = 0.f;
    int   kp = 0, n0g = 0;
    if (tid < 220) {
        kp  = tid % 44;
        n0g = (tid / 44) * 8;
        const int k0 = 2 * kp, k1 = k0 + 1;
#pragma unroll
        for (int u = 0; u < 8; u++) { bw[u] = 0.f; cw[u] = 0.f; }
        const bool g4 = (n0g == 32);          // n 32..39: dot column + zero pad
        if (g4) {
            bw[0] = 1.f; cw[0] = 1.f;         // n=32 gets (t_k0, t_k1)
            if (k0 < 64) {
                t0 = (k0 < 32) ? W_tgt[(size_t)tgt * 32 + k0]
                               : W_reg[(size_t)treg * 32 + k0 - 32];
                t1 = (k1 < 32) ? W_tgt[(size_t)tgt * 32 + k1]
                               : W_reg[(size_t)treg * 32 + k1 - 32];
            }
        } else if (k0 < 64) {
            float4 x0 = *(const float4*)(attn1_W + k0 * 32 + n0g);
            float4 x1 = *(const float4*)(attn1_W + k0 * 32 + n0g + 4);
            float4 y0 = *(const float4*)(attn1_W + k1 * 32 + n0g);
            float4 y1 = *(const float4*)(attn1_W + k1 * 32 + n0g + 4);
            bw[0]=x0.x; bw[1]=x0.y; bw[2]=x0.z; bw[3]=x0.w;
            bw[4]=x1.x; bw[5]=x1.y; bw[6]=x1.z; bw[7]=x1.w;
            cw[0]=y0.x; cw[1]=y0.y; cw[2]=y0.z; cw[3]=y0.w;
            cw[4]=y1.x; cw[5]=y1.y; cw[6]=y1.z; cw[7]=y1.w;
            t0 = (k0 < 32) ? W_tgt[(size_t)tgt * 32 + k0]
                           : W_reg[(size_t)treg * 32 + k0 - 32];
            t1 = (k1 < 32) ? W_tgt[(size_t)tgt * 32 + k1]
                           : W_reg[(size_t)treg * 32 + k1 - 32];
        } else if (k0 == 64) {                // dist-feature weight rows
            float4 x0 = *(const float4*)(attn1_W + 64 * 32 + n0g);
            float4 x1 = *(const float4*)(attn1_W + 64 * 32 + n0g + 4);
            float4 y0 = *(const float4*)(attn1_W + 65 * 32 + n0g);
            float4 y1 = *(const float4*)(attn1_W + 65 * 32 + n0g + 4);
            bw[0]=x0.x; bw[1]=x0.y; bw[2]=x0.z; bw[3]=x0.w;
            bw[4]=x1.x; bw[5]=x1.y; bw[6]=x1.z; bw[7]=x1.w;
            cw[0]=y0.x; cw[1]=y0.y; cw[2]=y0.z; cw[3]=y0.w;
            cw[4]=y1.x; cw[5]=y1.y; cw[6]=y1.z; cw[7]=y1.w;
            t0 = 1.f; t1 = 1.f;
        } else if (k0 == 66) {                // bias feature row
            float4 x0 = *(const float4*)(attn1_b + n0g);
            float4 x1 = *(const float4*)(attn1_b + n0g + 4);
            bw[0]=x0.x; bw[1]=x0.y; bw[2]=x0.z; bw[3]=x0.w;
            bw[4]=x1.x; bw[5]=x1.y; bw[6]=x1.z; bw[7]=x1.w;
            t0 = 1.f;                          // t1=0 -> k67 column zero
        }
        // kp >= 34 (non-g4): all zero
    }

    // ---- tile1 init: row = lane. word1 = (k66=1.0, k67=0); rest 0
    {
        uint4* r = (uint4*)(myA + T0_BYTES + lane * 48);
        r[0] = make_uint4(0u, 0x00003F80u, 0u, 0u);
        r[1] = make_uint4(0u, 0u, 0u, 0u);
        r[2] = make_uint4(0u, 0u, 0u, 0u);
    }

    // ---- dist features -> tile1 word0 (independent of everything above)
    {
        const float dw00 = dist_W[0] * 100.f, dw01 = dist_W[1] * 100.f;
        const float dw10 = dist_W[2] * 100.f, dw11 = dist_W[3] * 100.f;
        float d0 = sigm(fmaf(ll.x, dw00, fmaf(ll.y, dw10, dist_b[0])));
        float d1 = sigm(fmaf(ll.x, dw01, fmaf(ll.y, dw11, dist_b[1])));
        *(uint32_t*)(myA + T0_BYTES + lane * 48) = cvt2bf(d1, d0);
    }

    // ---- B-fill stores (after loads land)
    if (tid < 220) {
#pragma unroll
        for (int u = 0; u < 8; u++) {
            ((uint32_t*)s_W)[(n0g + u) * (WB_STRIDE / 2) + kp] =
                cvt2bf(t1 * cw[u], t0 * bw[u]);
        }
    }

    // ---- gather + cvt + swizzled store (4 lanes cooperate per position row)
    {
        const int c    = lane & 7;     // fp32 16B-chunk within the 128B table row
        const int rsel = lane >> 3;    // which of 4 rows this lane serves
#pragma unroll
        for (int q = 0; q < 8; q++) {
            int prow = 4 * q + rsel;   // local position 0..31
            int ii = __shfl_sync(0xffffffffu, idxv, prow);
            int rr = __shfl_sync(0xffffffffu, regv, prow);
            float4 eh = *(const float4*)(W_hist + (size_t)ii * 32 + 4 * c);
            float4 er = *(const float4*)(W_reg  + (size_t)rr * 32 + 4 * c);
            uint2 hv = make_uint2(cvt2bf(eh.y, eh.x), cvt2bf(eh.w, eh.z));
            uint2 rv = make_uint2(cvt2bf(er.y, er.x), cvt2bf(er.w, er.z));
            // bf16 dest: hist -> 16B-chunks 0..3, reg -> 4..7 (SW128 xor row&7)
            uint32_t half8 = (c & 1) << 3;
            uint32_t a0 = prow * 128 + ((((c >> 1)    ) ^ (prow & 7)) << 4) + half8;
            uint32_t a1 = prow * 128 + ((((c >> 1) + 4) ^ (prow & 7)) << 4) + half8;
            *(uint2*)(myA + a0) = hv;
            *(uint2*)(myA + a1) = rv;
        }
    }
    __syncthreads();   // the ONLY barrier: A tiles + B weights visible

    // ---- MMA: 2 m-tiles x 5 n-tiles x 5 k-steps
    float d[2][5][4];
#pragma unroll
    for (int mt = 0; mt < 2; mt++)
#pragma unroll
        for (int nn = 0; nn < 5; nn++)
#pragma unroll
            for (int i = 0; i < 4; i++) d[mt][nn][i] = 0.f;

    const uint32_t aT0 = (uint32_t)__cvta_generic_to_shared(myA);
    const uint32_t aT1 = aT0 + T0_BYTES;
    const uint32_t wB  = (uint32_t)__cvta_generic_to_shared(s_W);

#pragma unroll
    for (int kk = 0; kk < 5; kk++) {
        uint32_t a[2][4];
#pragma unroll
        for (int mt = 0; mt < 2; mt++) {
            int row = 16 * mt + (lane & 15);
            uint32_t addr;
            if (kk < 4) {
                int chunk = 2 * kk + (lane >> 4);
                addr = aT0 + row * 128 + ((chunk ^ (row & 7)) << 4);
            } else {
                addr = aT1 + row * 48 + ((lane >> 4) << 4);
            }
            ldsm_x4(addr, a[mt][0], a[mt][1], a[mt][2], a[mt][3]);
        }
#pragma unroll
        for (int nn = 0; nn < 5; nn++) {
            uint32_t b0, b1;
            int nrow = 8 * nn + (lane & 7);
            uint32_t baddr = wB + nrow * (WB_STRIDE * 2) + ((lane & 8) ? 16 : 0)
                           + kk * 32;
            ldsm_x2(baddr, b0, b1);
            mma16816(d[0][nn], a[0], b0, b1);
            mma16816(d[1][nn], a[1], b0, b1);
        }
    }

    // ---- epilogue: relu(hid) . w2, dot from col 32, masked exp, reduce
    float v00 = 0.f, v01 = 0.f, v10 = 0.f, v11 = 0.f;
#pragma unroll
    for (int nn = 0; nn < 4; nn++) {
        float w2a = w2v[nn].x;
        float w2b = w2v[nn].y;
        v00 = fmaf(fmaxf(d[0][nn][0], 0.f), w2a, fmaf(fmaxf(d[0][nn][1], 0.f), w2b, v00));
        v01 = fmaf(fmaxf(d[0][nn][2], 0.f), w2a, fmaf(fmaxf(d[0][nn][3], 0.f), w2b, v01));
        v10 = fmaf(fmaxf(d[1][nn][0], 0.f), w2a, fmaf(fmaxf(d[1][nn][1], 0.f), w2b, v10));
        v11 = fmaf(fmaxf(d[1][nn][2], 0.f), w2a, fmaf(fmaxf(d[1][nn][3], 0.f), w2b, v11));
    }
#pragma unroll
    for (int off = 1; off <= 2; off <<= 1) {
        v00 += __shfl_xor_sync(0xffffffffu, v00, off);
        v01 += __shfl_xor_sync(0xffffffffu, v01, off);
        v10 += __shfl_xor_sync(0xffffffffu, v10, off);
        v11 += __shfl_xor_sync(0xffffffffu, v11, off);
    }
    // dots live in tig==0 lanes at nn=4 (col 32): c0 = row gid, c2 = row gid+8
    int srcl = lane & ~3;
    float q00 = __shfl_sync(0xffffffffu, d[0][4][0], srcl);
    float q01 = __shfl_sync(0xffffffffu, d[0][4][2], srcl);
    float q10 = __shfl_sync(0xffffffffu, d[1][4][0], srcl);
    float q11 = __shfl_sync(0xffffffffu, d[1][4][2], srcl);

    float score = (tig == 0) ? v00 : (tig == 1) ? v01 : (tig == 2) ? v10 : v11;
    float dotv  = (tig == 0) ? q00 : (tig == 1) ? q01 : (tig == 2) ? q10 : q11;

    int posl2 = gid + 8 * tig;                       // local row this lane owns
    int idx   = __shfl_sync(0xffffffffu, idxv, posl2);
    bool ok   = (idx != tgt) && (tb + posl2 < HH);
    float e   = ok ? __expf(score) : 0.f;
    float se  = e;
    float sp  = e * dotv;
#pragma unroll
    for (int off = 16; off; off >>= 1) {
        se += __shfl_xor_sync(0xffffffffu, se, off);
        sp += __shfl_xor_sync(0xffffffffu, sp, off);
    }
    if (lane == 0) s_red[w] = make_float2(se, sp);
    __syncthreads();
    if (tid == 0) {
        float SE = 0.f, SP = 0.f;
#pragma unroll
        for (int i = 0; i < NWARP; i++) { SE += s_red[i].x; SP += s_red[i].y; }
        out[b] = sigm(SP * rsqrtf(SE));   // BETA=0.5: pred = SP / sqrt(SE)
    }
}

extern "C" void kernel_launch(void* const* d_in, const int* in_sizes, int n_in,
                              void* d_out, int out_size) {
    const int B = in_sizes[1];   // target is [B]
    nais_kernel<<<B, THREADS>>>(
        (const int*)  d_in[0],   // history [B,H]
        (const int*)  d_in[1],   // target [B]
        (const int*)  d_in[2],   // history_region [B,H]
        (const int*)  d_in[3],   // target_region [B]
        (const float*)d_in[4],   // target_lat_long [B,H,2]
        (const float*)d_in[5],   // W_hist
        (const float*)d_in[6],   // W_tgt
        (const float*)d_in[7],   // W_reg
        (const float*)d_in[8],   // attn1_W [66,32]
        (const float*)d_in[9],   // attn1_b [32]
        (const float*)d_in[10],  // attn2_W [32,1]
        (const float*)d_in[11],  // dist_W [2,2]
        (const float*)d_in[12],  // dist_b [2]
        (float*)d_out);
}

// round 7
// speedup vs baseline: 4.5946x; 1.1055x over previous
#include <cuda_runtime.h>
#include <cuda_bf16.h>
#include <cstdint>

#define HH      200
#define NWARP   7
#define THREADS 224

// per-warp A staging: tile0 = 32 rows x 128B (SW128-swizzled bf16, k 0..63)
//                     tile1 = 32 rows x 48B  (k 64..79: dist, const-1, pad)
#define T0_BYTES (32 * 128)
#define T1_BYTES (32 * 48)
#define AW_BYTES (T0_BYTES + T1_BYTES)

// B weight matrix: [40 n-rows][88 k bf16] (stride 176B, conflict-free LDSM)
#define WB_STRIDE 88
#define WB_BYTES  (40 * WB_STRIDE * 2)   // 7040

// Batch-independent B matrix, prebuilt by build_B kernel:
//   n<32 : k<66 -> attn1_W[k][n], k=66 -> attn1_b[n], else 0
//   n=32 : k<64 -> 1.0 (dot column; A holds products), else 0
//   n>32 : 0
__device__ __align__(16) __nv_bfloat16 g_B[40 * WB_STRIDE];

__device__ __forceinline__ uint32_t cvt2bf(float hi, float lo) {
    uint32_t r;
    asm("cvt.rn.bf16x2.f32 %0, %1, %2;" : "=r"(r) : "f"(hi), "f"(lo));
    return r;
}
__device__ __forceinline__ float sigm(float x) {
    return __fdividef(1.f, 1.f + __expf(-x));
}
__device__ __forceinline__ void ldsm_x4(uint32_t addr, uint32_t& r0, uint32_t& r1,
                                        uint32_t& r2, uint32_t& r3) {
    asm volatile("ldmatrix.sync.aligned.m8n8.x4.shared.b16 {%0,%1,%2,%3}, [%4];"
                 : "=r"(r0), "=r"(r1), "=r"(r2), "=r"(r3) : "r"(addr));
}
__device__ __forceinline__ void ldsm_x2(uint32_t addr, uint32_t& r0, uint32_t& r1) {
    asm volatile("ldmatrix.sync.aligned.m8n8.x2.shared.b16 {%0,%1}, [%2];"
                 : "=r"(r0), "=r"(r1) : "r"(addr));
}
__device__ __forceinline__ void mma16816(float* d, const uint32_t* a,
                                         uint32_t b0, uint32_t b1) {
    asm volatile(
        "mma.sync.aligned.m16n8k16.row.col.f32.bf16.bf16.f32 "
        "{%0,%1,%2,%3}, {%4,%5,%6,%7}, {%8,%9}, {%0,%1,%2,%3};"
        : "+f"(d[0]), "+f"(d[1]), "+f"(d[2]), "+f"(d[3])
        : "r"(a[0]), "r"(a[1]), "r"(a[2]), "r"(a[3]), "r"(b0), "r"(b1));
}

// ---- prologue: build the constant B matrix (one tiny block) ----------------
__global__ void build_B(const float* __restrict__ attn1_W,
                        const float* __restrict__ attn1_b) {
    for (int wd = threadIdx.x; wd < 40 * (WB_STRIDE / 2); wd += blockDim.x) {
        int n  = wd / (WB_STRIDE / 2);
        int kp = wd % (WB_STRIDE / 2);
        int k0 = 2 * kp, k1 = k0 + 1;
        auto wv = [&](int k) -> float {
            if (n < 32) {
                if (k < 66)  return attn1_W[k * 32 + n];
                if (k == 66) return attn1_b[n];
                return 0.f;
            }
            if (n == 32) return (k < 64) ? 1.f : 0.f;
            return 0.f;
        };
        ((uint32_t*)g_B)[n * (WB_STRIDE / 2) + kp] = cvt2bf(wv(k1), wv(k0));
    }
}

// ---------------------------------------------------------------------------
// One block per batch row. 7 warps; warp w owns positions [32w, 32w+32).
//
// MMA: D[200pad, 40] = A[200pad, 80] x B[80, 40]   (bf16 in, fp32 acc)
//   A rows = positions. k 0..63 = h_emb_k * t_k (PRODUCTS), k 64,65 = dist,
//   k 66 = 1.0 (bias feature), k 67..79 = 0.
//   B is the constant g_B -> bulk cp.async, no per-block weight math.
//   D[:,32] = sum_k p_k = dot(h_emb, t_emb) (B col 32 = ones).
// ---------------------------------------------------------------------------
__global__ __launch_bounds__(THREADS, 4)
void nais_kernel(const int*   __restrict__ history,
                 const int*   __restrict__ target,
                 const int*   __restrict__ history_region,
                 const int*   __restrict__ target_region,
                 const float* __restrict__ lat_long,
                 const float* __restrict__ W_hist,
                 const float* __restrict__ W_tgt,
                 const float* __restrict__ W_reg,
                 const float* __restrict__ attn2_W,
                 const float* __restrict__ dist_W,
                 const float* __restrict__ dist_b,
                 float*       __restrict__ out)
{
    __shared__ __align__(16) unsigned char s_A[NWARP * AW_BYTES];
    __shared__ __align__(16) __nv_bfloat16 s_W[40 * WB_STRIDE];
    __shared__ float2 s_red[NWARP];

    const int b    = blockIdx.x;
    const int tid  = threadIdx.x;
    const int w    = tid >> 5;
    const int lane = tid & 31;
    const int gid  = lane >> 2;
    const int tig  = lane & 3;
    const int base = b * HH;
    const int tgt  = target[b];
    const int treg = target_region[b];
    const int tb   = 32 * w;
    const int c    = lane & 7;     // fp32 16B-chunk within the 128B table row

    unsigned char* myA = s_A + w * AW_BYTES;

    // ---- B matrix: bulk async copy g_B -> s_W (no registers, no deps)
    {
        const uint32_t dstW = (uint32_t)__cvta_generic_to_shared(s_W);
        const char* src = (const char*)g_B;
#pragma unroll
        for (int off = tid * 16; off < WB_BYTES; off += THREADS * 16) {
            asm volatile("cp.async.ca.shared.global [%0], [%1], 16;"
                         :: "r"(dstW + off), "l"(src + off));
        }
        asm volatile("cp.async.commit_group;");
    }

    // ---- per-warp position indices + lat_long (longest chains first)
    const int posl = min(tb + lane, HH - 1);
    const int idxv = history[base + posl];
    const int regv = history_region[base + posl];
    float2 ll = *(const float2*)(lat_long + (size_t)(base + posl) * 2);

    // ---- this lane's target-embedding chunk (uniform per c; L2/L1 hot)
    const float4 th = *(const float4*)(W_tgt + (size_t)tgt * 32 + 4 * c);
    const float4 tr = *(const float4*)(W_reg + (size_t)treg * 32 + 4 * c);

    // ---- epilogue weights (hoisted; independent)
    float2 w2v[4];
#pragma unroll
    for (int nn = 0; nn < 4; nn++)
        w2v[nn] = *(const float2*)(attn2_W + 8 * nn + 2 * tig);

    // ---- tile1 init: row = lane. word1 = (k66=1.0, k67=0); rest 0
    {
        uint4* r = (uint4*)(myA + T0_BYTES + lane * 48);
        r[0] = make_uint4(0u, 0x00003F80u, 0u, 0u);
        r[1] = make_uint4(0u, 0u, 0u, 0u);
        r[2] = make_uint4(0u, 0u, 0u, 0u);
    }

    // ---- dist features -> tile1 word0
    {
        const float dw00 = dist_W[0] * 100.f, dw01 = dist_W[1] * 100.f;
        const float dw10 = dist_W[2] * 100.f, dw11 = dist_W[3] * 100.f;
        float d0 = sigm(fmaf(ll.x, dw00, fmaf(ll.y, dw10, dist_b[0])));
        float d1 = sigm(fmaf(ll.x, dw01, fmaf(ll.y, dw11, dist_b[1])));
        *(uint32_t*)(myA + T0_BYTES + lane * 48) = cvt2bf(d1, d0);
    }

    // ---- gather + product + cvt + swizzled store (4 lanes per position row)
    {
        const int rsel = lane >> 3;    // which of 4 rows this lane serves
#pragma unroll
        for (int q = 0; q < 8; q++) {
            int prow = 4 * q + rsel;   // local position 0..31
            int ii = __shfl_sync(0xffffffffu, idxv, prow);
            int rr = __shfl_sync(0xffffffffu, regv, prow);
            float4 eh = *(const float4*)(W_hist + (size_t)ii * 32 + 4 * c);
            float4 er = *(const float4*)(W_reg  + (size_t)rr * 32 + 4 * c);
            uint2 hv = make_uint2(cvt2bf(eh.y * th.y, eh.x * th.x),
                                  cvt2bf(eh.w * th.w, eh.z * th.z));
            uint2 rv = make_uint2(cvt2bf(er.y * tr.y, er.x * tr.x),
                                  cvt2bf(er.w * tr.w, er.z * tr.z));
            // bf16 dest: hist -> 16B-chunks 0..3, reg -> 4..7 (SW128 xor row&7)
            uint32_t half8 = (c & 1) << 3;
            uint32_t a0 = prow * 128 + ((((c >> 1)    ) ^ (prow & 7)) << 4) + half8;
            uint32_t a1 = prow * 128 + ((((c >> 1) + 4) ^ (prow & 7)) << 4) + half8;
            *(uint2*)(myA + a0) = hv;
            *(uint2*)(myA + a1) = rv;
        }
    }
    asm volatile("cp.async.wait_group 0;" ::: "memory");
    __syncthreads();   // the ONLY barrier: A tiles + B weights visible

    // ---- MMA: 2 m-tiles x 5 n-tiles x 5 k-steps
    float d[2][5][4];
#pragma unroll
    for (int mt = 0; mt < 2; mt++)
#pragma unroll
        for (int nn = 0; nn < 5; nn++)
#pragma unroll
            for (int i = 0; i < 4; i++) d[mt][nn][i] = 0.f;

    const uint32_t aT0 = (uint32_t)__cvta_generic_to_shared(myA);
    const uint32_t aT1 = aT0 + T0_BYTES;
    const uint32_t wB  = (uint32_t)__cvta_generic_to_shared(s_W);

#pragma unroll
    for (int kk = 0; kk < 5; kk++) {
        uint32_t a[2][4];
#pragma unroll
        for (int mt = 0; mt < 2; mt++) {
            int row = 16 * mt + (lane & 15);
            uint32_t addr;
            if (kk < 4) {
                int chunk = 2 * kk + (lane >> 4);
                addr = aT0 + row * 128 + ((chunk ^ (row & 7)) << 4);
            } else {
                addr = aT1 + row * 48 + ((lane >> 4) << 4);
            }
            ldsm_x4(addr, a[mt][0], a[mt][1], a[mt][2], a[mt][3]);
        }
#pragma unroll
        for (int nn = 0; nn < 5; nn++) {
            uint32_t b0, b1;
            int nrow = 8 * nn + (lane & 7);
            uint32_t baddr = wB + nrow * (WB_STRIDE * 2) + ((lane & 8) ? 16 : 0)
                           + kk * 32;
            ldsm_x2(baddr, b0, b1);
            mma16816(d[0][nn], a[0], b0, b1);
            mma16816(d[1][nn], a[1], b0, b1);
        }
    }

    // ---- epilogue: relu(hid) . w2, dot from col 32, masked exp, reduce
    float v00 = 0.f, v01 = 0.f, v10 = 0.f, v11 = 0.f;
#pragma unroll
    for (int nn = 0; nn < 4; nn++) {
        float w2a = w2v[nn].x;
        float w2b = w2v[nn].y;
        v00 = fmaf(fmaxf(d[0][nn][0], 0.f), w2a, fmaf(fmaxf(d[0][nn][1], 0.f), w2b, v00));
        v01 = fmaf(fmaxf(d[0][nn][2], 0.f), w2a, fmaf(fmaxf(d[0][nn][3], 0.f), w2b, v01));
        v10 = fmaf(fmaxf(d[1][nn][0], 0.f), w2a, fmaf(fmaxf(d[1][nn][1], 0.f), w2b, v10));
        v11 = fmaf(fmaxf(d[1][nn][2], 0.f), w2a, fmaf(fmaxf(d[1][nn][3], 0.f), w2b, v11));
    }
#pragma unroll
    for (int off = 1; off <= 2; off <<= 1) {
        v00 += __shfl_xor_sync(0xffffffffu, v00, off);
        v01 += __shfl_xor_sync(0xffffffffu, v01, off);
        v10 += __shfl_xor_sync(0xffffffffu, v10, off);
        v11 += __shfl_xor_sync(0xffffffffu, v11, off);
    }
    // dots live in tig==0 lanes at nn=4 (col 32): c0 = row gid, c2 = row gid+8
    int srcl = lane & ~3;
    float q00 = __shfl_sync(0xffffffffu, d[0][4][0], srcl);
    float q01 = __shfl_sync(0xffffffffu, d[0][4][2], srcl);
    float q10 = __shfl_sync(0xffffffffu, d[1][4][0], srcl);
    float q11 = __shfl_sync(0xffffffffu, d[1][4][2], srcl);

    float score = (tig == 0) ? v00 : (tig == 1) ? v01 : (tig == 2) ? v10 : v11;
    float dotv  = (tig == 0) ? q00 : (tig == 1) ? q01 : (tig == 2) ? q10 : q11;

    int posl2 = gid + 8 * tig;                       // local row this lane owns
    int idx   = __shfl_sync(0xffffffffu, idxv, posl2);
    bool ok   = (idx != tgt) && (tb + posl2 < HH);
    float e   = ok ? __expf(score) : 0.f;
    float se  = e;
    float sp  = e * dotv;
#pragma unroll
    for (int off = 16; off; off >>= 1) {
        se += __shfl_xor_sync(0xffffffffu, se, off);
        sp += __shfl_xor_sync(0xffffffffu, sp, off);
    }
    if (lane == 0) s_red[w] = make_float2(se, sp);
    __syncthreads();
    if (tid == 0) {
        float SE = 0.f, SP = 0.f;
#pragma unroll
        for (int i = 0; i < NWARP; i++) { SE += s_red[i].x; SP += s_red[i].y; }
        out[b] = sigm(SP * rsqrtf(SE));   // BETA=0.5: pred = SP / sqrt(SE)
    }
}

extern "C" void kernel_launch(void* const* d_in, const int* in_sizes, int n_in,
                              void* d_out, int out_size) {
    const int B = in_sizes[1];   // target is [B]
    build_B<<<1, 256>>>((const float*)d_in[8], (const float*)d_in[9]);
    nais_kernel<<<B, THREADS>>>(
        (const int*)  d_in[0],   // history [B,H]
        (const int*)  d_in[1],   // target [B]
        (const int*)  d_in[2],   // history_region [B,H]
        (const int*)  d_in[3],   // target_region [B]
        (const float*)d_in[4],   // target_lat_long [B,H,2]
        (const float*)d_in[5],   // W_hist
        (const float*)d_in[6],   // W_tgt
        (const float*)d_in[7],   // W_reg
        (const float*)d_in[10],  // attn2_W [32,1]
        (const float*)d_in[11],  // dist_W [2,2]
        (const float*)d_in[12],  // dist_b [2]
        (float*)d_out);
}

// round 8
// speedup vs baseline: 4.6753x; 1.0176x over previous
#include <cuda_runtime.h>
#include <cuda_bf16.h>
#include <cstdint>

#define HH      200
#define NWARP   7
#define THREADS 224

// per-warp A staging: tile0 = 32 rows x 128B (SW128-swizzled bf16, k 0..63)
//                     tile1 = 32 rows x 32B  (k 64..79: dist, const-1, pad)
#define T0_BYTES (32 * 128)
#define T1_BYTES (32 * 32)
#define AW_BYTES (T0_BYTES + T1_BYTES)

// B matrix in mma fragment order: [kk=5][nn=4][r=2][lane=32] bf16x2 words.
// Word(kk,nn,r,l) = pack( B[k0+1][n], B[k0][n] ),
//   n = 8*nn + (l>>2),  k0 = 16*kk + 8*r + 2*(l&3)
//   B[k][n]: k<66 -> attn1_W[k][n], k==66 -> attn1_b[n], else 0.
__device__ __align__(16) uint32_t g_Bfrag[5 * 4 * 2 * 32];

__device__ __forceinline__ uint32_t cvt2bf(float hi, float lo) {
    uint32_t r;
    asm("cvt.rn.bf16x2.f32 %0, %1, %2;" : "=r"(r) : "f"(hi), "f"(lo));
    return r;
}
__device__ __forceinline__ float sigm(float x) {
    return __fdividef(1.f, 1.f + __expf(-x));
}
__device__ __forceinline__ void ldsm_x4(uint32_t addr, uint32_t& r0, uint32_t& r1,
                                        uint32_t& r2, uint32_t& r3) {
    asm volatile("ldmatrix.sync.aligned.m8n8.x4.shared.b16 {%0,%1,%2,%3}, [%4];"
                 : "=r"(r0), "=r"(r1), "=r"(r2), "=r"(r3) : "r"(addr));
}
__device__ __forceinline__ void mma16816(float* d, const uint32_t* a,
                                         uint32_t b0, uint32_t b1) {
    asm volatile(
        "mma.sync.aligned.m16n8k16.row.col.f32.bf16.bf16.f32 "
        "{%0,%1,%2,%3}, {%4,%5,%6,%7}, {%8,%9}, {%0,%1,%2,%3};"
        : "+f"(d[0]), "+f"(d[1]), "+f"(d[2]), "+f"(d[3])
        : "r"(a[0]), "r"(a[1]), "r"(a[2]), "r"(a[3]), "r"(b0), "r"(b1));
}

// ---- prologue: build fragment-order B (one tiny block) ---------------------
__global__ void build_Bfrag(const float* __restrict__ attn1_W,
                            const float* __restrict__ attn1_b) {
    for (int t = threadIdx.x; t < 5 * 4 * 2 * 32; t += blockDim.x) {
        int l   = t & 31;
        int r   = (t >> 5) & 1;
        int nn  = (t >> 6) & 3;
        int kk  = t >> 8;
        int n   = 8 * nn + (l >> 2);
        int k0  = 16 * kk + 8 * r + 2 * (l & 3);
        auto bval = [&](int k) -> float {
            if (k < 66)  return attn1_W[k * 32 + n];
            if (k == 66) return attn1_b[n];
            return 0.f;
        };
        g_Bfrag[t] = cvt2bf(bval(k0 + 1), bval(k0));
    }
}

// ---------------------------------------------------------------------------
// One block per batch row. 7 warps; warp w owns positions [32w, 32w+32).
// Warps are fully independent until the final 56B reduction (no pre-MMA
// block barrier): A tiles are per-warp private, B fragments come straight
// from g_Bfrag via per-warp coalesced LDG (L1-hot, batch-invariant).
//
// MMA: D[32, 32] per warp = A[32, 80] x B[80, 32]  (bf16 in, fp32 acc)
//   A rows = positions. k 0..63 = h_emb_k * t_k (products), k 64,65 = dist,
//   k 66 = 1.0 (bias feature), k 67..79 = 0.
//   dot(h_emb, t_emb) computed in fp32 during the gather (8-lane butterfly).
// ---------------------------------------------------------------------------
__global__ __launch_bounds__(THREADS, 4)
void nais_kernel(const int*   __restrict__ history,
                 const int*   __restrict__ target,
                 const int*   __restrict__ history_region,
                 const int*   __restrict__ target_region,
                 const float* __restrict__ lat_long,
                 const float* __restrict__ W_hist,
                 const float* __restrict__ W_tgt,
                 const float* __restrict__ W_reg,
                 const float* __restrict__ attn2_W,
                 const float* __restrict__ dist_W,
                 const float* __restrict__ dist_b,
                 float*       __restrict__ out)
{
    __shared__ __align__(16) unsigned char s_A[NWARP * AW_BYTES];
    __shared__ float  s_dot[NWARP * 32];
    __shared__ float2 s_red[NWARP];

    const int b    = blockIdx.x;
    const int tid  = threadIdx.x;
    const int w    = tid >> 5;
    const int lane = tid & 31;
    const int gid  = lane >> 2;
    const int tig  = lane & 3;
    const int base = b * HH;
    const int tgt  = target[b];
    const int treg = target_region[b];
    const int tb   = 32 * w;
    const int c    = lane & 7;     // fp32 16B-chunk within the 128B table row

    unsigned char* myA = s_A + w * AW_BYTES;

    // ---- this lane's target-embedding chunk (uniform per c; L2/L1 hot)
    const float4 th = *(const float4*)(W_tgt + (size_t)tgt * 32 + 4 * c);
    const float4 tr = *(const float4*)(W_reg + (size_t)treg * 32 + 4 * c);

    // ---- epilogue weights (hoisted; independent)
    float2 w2v[4];
#pragma unroll
    for (int nn = 0; nn < 4; nn++)
        w2v[nn] = *(const float2*)(attn2_W + 8 * nn + 2 * tig);

    // ---- tile1 init: row = lane. chunk0 = (dist placeholder, k66=1.0, 0, 0)
    {
        uint4* r = (uint4*)(myA + T0_BYTES + lane * 32);
        r[0] = make_uint4(0u, 0x00003F80u, 0u, 0u);
        r[1] = make_uint4(0u, 0u, 0u, 0u);
    }

    // ---- dist features -> tile1 word0 (same lane, program-ordered after init)
    {
        const int posl = min(tb + lane, HH - 1);
        float2 ll = *(const float2*)(lat_long + (size_t)(base + posl) * 2);
        const float dw00 = dist_W[0] * 100.f, dw01 = dist_W[1] * 100.f;
        const float dw10 = dist_W[2] * 100.f, dw11 = dist_W[3] * 100.f;
        float d0 = sigm(fmaf(ll.x, dw00, fmaf(ll.y, dw10, dist_b[0])));
        float d1 = sigm(fmaf(ll.x, dw01, fmaf(ll.y, dw11, dist_b[1])));
        *(uint32_t*)(myA + T0_BYTES + lane * 32) = cvt2bf(d1, d0);
    }

    // ---- gather + product + fp32 dot + cvt + swizzled store
    {
        const int rsel = lane >> 3;    // which of 4 rows this lane serves per q
#pragma unroll
        for (int q = 0; q < 8; q++) {
            int prow = 4 * q + rsel;   // local position 0..31
            int gpos = min(tb + prow, HH - 1);
            int ii = history[base + gpos];          // 8-lane broadcast load
            int rr = history_region[base + gpos];
            float4 eh = *(const float4*)(W_hist + (size_t)ii * 32 + 4 * c);
            float4 er = *(const float4*)(W_reg  + (size_t)rr * 32 + 4 * c);
            float ph0 = eh.x * th.x, ph1 = eh.y * th.y;
            float ph2 = eh.z * th.z, ph3 = eh.w * th.w;
            float pr0 = er.x * tr.x, pr1 = er.y * tr.y;
            float pr2 = er.z * tr.z, pr3 = er.w * tr.w;
            uint2 hv = make_uint2(cvt2bf(ph1, ph0), cvt2bf(ph3, ph2));
            uint2 rv = make_uint2(cvt2bf(pr1, pr0), cvt2bf(pr3, pr2));
            // bf16 dest: hist -> 16B-chunks 0..3, reg -> 4..7 (SW128 xor row&7)
            uint32_t half8 = (c & 1) << 3;
            uint32_t a0 = prow * 128 + ((((c >> 1)    ) ^ (prow & 7)) << 4) + half8;
            uint32_t a1 = prow * 128 + ((((c >> 1) + 4) ^ (prow & 7)) << 4) + half8;
            *(uint2*)(myA + a0) = hv;
            *(uint2*)(myA + a1) = rv;
            // fp32 dot over the 8 lanes sharing this row
            float part = ((ph0 + ph1) + (ph2 + ph3)) + ((pr0 + pr1) + (pr2 + pr3));
            part += __shfl_xor_sync(0xffffffffu, part, 1);
            part += __shfl_xor_sync(0xffffffffu, part, 2);
            part += __shfl_xor_sync(0xffffffffu, part, 4);
            if (c == 0) s_dot[w * 32 + prow] = part;
        }
    }
    __syncwarp();   // per-warp only: A tile + s_dot visible to this warp

    // ---- MMA: 2 m-tiles x 4 n-tiles x 5 k-steps; B frags via LDG
    float d[2][4][4];
#pragma unroll
    for (int mt = 0; mt < 2; mt++)
#pragma unroll
        for (int nn = 0; nn < 4; nn++)
#pragma unroll
            for (int i = 0; i < 4; i++) d[mt][nn][i] = 0.f;

    const uint32_t aT0 = (uint32_t)__cvta_generic_to_shared(myA);
    const uint32_t aT1 = aT0 + T0_BYTES;

#pragma unroll
    for (int kk = 0; kk < 5; kk++) {
        uint32_t a[2][4];
#pragma unroll
        for (int mt = 0; mt < 2; mt++) {
            int row = 16 * mt + (lane & 15);
            uint32_t addr;
            if (kk < 4) {
                int chunk = 2 * kk + (lane >> 4);
                addr = aT0 + row * 128 + ((chunk ^ (row & 7)) << 4);
            } else {
                addr = aT1 + row * 32 + ((lane >> 4) << 4);
            }
            ldsm_x4(addr, a[mt][0], a[mt][1], a[mt][2], a[mt][3]);
        }
#pragma unroll
        for (int nn = 0; nn < 4; nn++) {
            uint32_t b0 = g_Bfrag[((kk * 4 + nn) * 2    ) * 32 + lane];
            uint32_t b1 = g_Bfrag[((kk * 4 + nn) * 2 + 1) * 32 + lane];
            mma16816(d[0][nn], a[0], b0, b1);
            mma16816(d[1][nn], a[1], b0, b1);
        }
    }

    // ---- epilogue: relu(hid) . w2, masked exp, reduce
    float v00 = 0.f, v01 = 0.f, v10 = 0.f, v11 = 0.f;
#pragma unroll
    for (int nn = 0; nn < 4; nn++) {
        float w2a = w2v[nn].x;
        float w2b = w2v[nn].y;
        v00 = fmaf(fmaxf(d[0][nn][0], 0.f), w2a, fmaf(fmaxf(d[0][nn][1], 0.f), w2b, v00));
        v01 = fmaf(fmaxf(d[0][nn][2], 0.f), w2a, fmaf(fmaxf(d[0][nn][3], 0.f), w2b, v01));
        v10 = fmaf(fmaxf(d[1][nn][0], 0.f), w2a, fmaf(fmaxf(d[1][nn][1], 0.f), w2b, v10));
        v11 = fmaf(fmaxf(d[1][nn][2], 0.f), w2a, fmaf(fmaxf(d[1][nn][3], 0.f), w2b, v11));
    }
#pragma unroll
    for (int off = 1; off <= 2; off <<= 1) {
        v00 += __shfl_xor_sync(0xffffffffu, v00, off);
        v01 += __shfl_xor_sync(0xffffffffu, v01, off);
        v10 += __shfl_xor_sync(0xffffffffu, v10, off);
        v11 += __shfl_xor_sync(0xffffffffu, v11, off);
    }
    float score = (tig == 0) ? v00 : (tig == 1) ? v01 : (tig == 2) ? v10 : v11;

    int posl2 = gid + 8 * tig;                       // local row this lane owns
    float dotv = s_dot[w * 32 + posl2];              // fp32 dot (conflict-free)
    int idx = history[base + min(tb + posl2, HH - 1)];
    bool ok = (idx != tgt) && (tb + posl2 < HH);
    float e  = ok ? __expf(score) : 0.f;
    float se = e;
    float sp = e * dotv;
#pragma unroll
    for (int off = 16; off; off >>= 1) {
        se += __shfl_xor_sync(0xffffffffu, se, off);
        sp += __shfl_xor_sync(0xffffffffu, sp, off);
    }
    if (lane == 0) s_red[w] = make_float2(se, sp);
    __syncthreads();
    if (tid == 0) {
        float SE = 0.f, SP = 0.f;
#pragma unroll
        for (int i = 0; i < NWARP; i++) { SE += s_red[i].x; SP += s_red[i].y; }
        out[b] = sigm(SP * rsqrtf(SE));   // BETA=0.5: pred = SP / sqrt(SE)
    }
}

extern "C" void kernel_launch(void* const* d_in, const int* in_sizes, int n_in,
                              void* d_out, int out_size) {
    const int B = in_sizes[1];   // target is [B]
    build_Bfrag<<<1, 256>>>((const float*)d_in[8], (const float*)d_in[9]);
    nais_kernel<<<B, THREADS>>>(
        (const int*)  d_in[0],   // history [B,H]
        (const int*)  d_in[1],   // target [B]
        (const int*)  d_in[2],   // history_region [B,H]
        (const int*)  d_in[3],   // target_region [B]
        (const float*)d_in[4],   // target_lat_long [B,H,2]
        (const float*)d_in[5],   // W_hist
        (const float*)d_in[6],   // W_tgt
        (const float*)d_in[7],   // W_reg
        (const float*)d_in[10],  // attn2_W [32,1]
        (const float*)d_in[11],  // dist_W [2,2]
        (const float*)d_in[12],  // dist_b [2]
        (float*)d_out);
}